// round 1
// baseline (speedup 1.0000x reference)
#include <cuda_runtime.h>
#include <cuda_bf16.h>
#include <math.h>

// Problem constants
#define Bn 4
#define Tn 1024
#define Cn 1024
#define Hn 16
#define Dn 64

// ---------------- scratch (no allocations allowed) ----------------
__device__ float g_qkv[Bn * Tn * 3 * Cn];        // 48 MB
__device__ float g_qt [Bn * Hn * Tn * Dn];       // 16 MB  q' = [cosh, sinh*u/n ...]
__device__ float g_kt [Bn * Hn * Tn * Dn];       // 16 MB  k' = [cosh, -sinh*u/n ...]
__device__ float g_vt [Bn * Hn * Tn * Dn];       // 16 MB  v head-major
__device__ float g_spk[Bn * Tn];
__device__ float g_y  [Bn * Tn * Cn];            // 16 MB

// ---------------- spike / surrogate kernel ----------------
__global__ void spike_kernel(const float* __restrict__ x,
                             const float* __restrict__ w_sur,
                             const float* __restrict__ b_sur,
                             const float* __restrict__ threshold,
                             float* __restrict__ spikes) {
    __shared__ float red[256];
    int bt = blockIdx.x;
    const float* xr = &x[(size_t)bt * Cn];
    float s = 0.f;
    for (int c = threadIdx.x; c < Cn; c += 256) s += xr[c] * w_sur[c];
    red[threadIdx.x] = s;
    __syncthreads();
    for (int o = 128; o; o >>= 1) {
        if (threadIdx.x < o) red[threadIdx.x] += red[threadIdx.x + o];
        __syncthreads();
    }
    if (threadIdx.x == 0) {
        float imp = 1.f / (1.f + expf(-(red[0] + b_sur[0])));
        spikes[bt] = imp > threshold[0] ? 1.f : 0.f;
    }
}

// ---------------- generic tiled SGEMM: C = A(MxK) @ B(KxN) + bias ----------------
// BM=128, BN=64, BK=16, 256 threads, each thread 8x4 outputs.
__global__ __launch_bounds__(256) void gemm_bias_kernel(
    const float* __restrict__ A, const float* __restrict__ Bm,
    const float* __restrict__ bias, float* __restrict__ Cm,
    int M, int N, int K) {
    __shared__ float As[16][132];   // [k][m], padded
    __shared__ float Bs[16][64];    // [k][n]

    int tid = threadIdx.x;
    int block_m = blockIdx.y * 128;
    int block_n = blockIdx.x * 64;
    int tm0 = (tid % 16) * 8;
    int tn0 = (tid / 16) * 4;

    float acc[8][4];
#pragma unroll
    for (int i = 0; i < 8; i++)
#pragma unroll
        for (int j = 0; j < 4; j++) acc[i][j] = 0.f;

    for (int k0 = 0; k0 < K; k0 += 16) {
        // load A tile 128x16 (2 float4 / thread), transpose into As[k][m]
#pragma unroll
        for (int it = 0; it < 2; it++) {
            int linear = (it * 256 + tid) * 4;
            int m = linear / 16;
            int k = linear % 16;
            float4 a = *(const float4*)&A[(size_t)(block_m + m) * K + k0 + k];
            As[k + 0][m] = a.x;
            As[k + 1][m] = a.y;
            As[k + 2][m] = a.z;
            As[k + 3][m] = a.w;
        }
        // load B tile 16x64 (1 float4 / thread)
        {
            int linear = tid * 4;
            int k = linear / 64;
            int n = linear % 64;
            *(float4*)&Bs[k][n] = *(const float4*)&Bm[(size_t)(k0 + k) * N + block_n + n];
        }
        __syncthreads();
#pragma unroll
        for (int kk = 0; kk < 16; kk++) {
            float a[8], b[4];
#pragma unroll
            for (int i = 0; i < 8; i++) a[i] = As[kk][tm0 + i];
#pragma unroll
            for (int j = 0; j < 4; j++) b[j] = Bs[kk][tn0 + j];
#pragma unroll
            for (int i = 0; i < 8; i++)
#pragma unroll
                for (int j = 0; j < 4; j++) acc[i][j] += a[i] * b[j];
        }
        __syncthreads();
    }
#pragma unroll
    for (int i = 0; i < 8; i++) {
        float* crow = &Cm[(size_t)(block_m + tm0 + i) * N + block_n + tn0];
#pragma unroll
        for (int j = 0; j < 4; j++) crow[j] = acc[i][j] + bias[block_n + tn0 + j];
    }
}

// ---------------- expmap0 transform ----------------
// one warp per (bt, h); writes qt, kt (space negated), vt in (b,h,t,d) layout
__global__ void transform_kernel(const float* __restrict__ qkv,
                                 float* __restrict__ qt,
                                 float* __restrict__ kt,
                                 float* __restrict__ vt) {
    int gw = (blockIdx.x * blockDim.x + threadIdx.x) >> 5;   // warp id
    int lane = threadIdx.x & 31;
    int bt = gw / Hn;
    int h = gw % Hn;
    int b = bt / Tn;
    int t = bt % Tn;

    const float* base = &qkv[(size_t)bt * (3 * Cn) + h * Dn];
    float2 uq = ((const float2*)base)[lane];
    float2 uk = ((const float2*)(base + Cn))[lane];
    float2 uv = ((const float2*)(base + 2 * Cn))[lane];

    // sum of squares over d>=1 (d = 2*lane and 2*lane+1; exclude d=0)
    float sq = uq.y * uq.y + (lane ? uq.x * uq.x : 0.f);
    float sk = uk.y * uk.y + (lane ? uk.x * uk.x : 0.f);
#pragma unroll
    for (int off = 16; off; off >>= 1) {
        sq += __shfl_xor_sync(0xFFFFFFFFu, sq, off);
        sk += __shfl_xor_sync(0xFFFFFFFFu, sk, off);
    }
    float u0q = __shfl_sync(0xFFFFFFFFu, uq.x, 0);
    float u0k = __shfl_sync(0xFFFFFFFFu, uk.x, 0);

    float nq = sqrtf(fmaxf(sq - u0q * u0q, 1e-8f));
    float nk = sqrtf(fmaxf(sk - u0k * u0k, 1e-8f));
    float fq = sinhf(nq) / nq;
    float fk = sinhf(nk) / nk;
    float tmq = coshf(nq);
    float tmk = coshf(nk);

    size_t out = (((size_t)(b * Hn + h)) * Tn + t) * Dn;
    float2 oq, ok;
    oq.x = lane ? fq * uq.x : tmq;
    oq.y = fq * uq.y;
    ok.x = lane ? -fk * uk.x : tmk;
    ok.y = -fk * uk.y;
    ((float2*)&qt[out])[lane] = oq;
    ((float2*)&kt[out])[lane] = ok;
    ((float2*)&vt[out])[lane] = uv;
}

// ---------------- causal Lorentz flash attention ----------------
// block = 64 threads, one query row per thread; key tiles of 32
#define TK 32
__global__ __launch_bounds__(64) void attn_kernel(
    const float* __restrict__ qt, const float* __restrict__ kt,
    const float* __restrict__ vt, const float* __restrict__ spikes,
    float* __restrict__ y) {
    __shared__ float Ks[TK][Dn];
    __shared__ float Vs[TK][Dn];

    int tid = threadIdx.x;
    int qtile = blockIdx.x;
    int h = blockIdx.y;
    int b = blockIdx.z;
    int i = qtile * 64 + tid;

    const float* qrow = &qt[(((size_t)(b * Hn + h)) * Tn + i) * Dn];
    float4 q[16];
#pragma unroll
    for (int d4 = 0; d4 < 16; d4++) q[d4] = ((const float4*)qrow)[d4];

    float acc[64];
#pragma unroll
    for (int d = 0; d < 64; d++) acc[d] = 0.f;
    float m = -1e30f, l = 0.f;

    const float* kbase = &kt[(((size_t)(b * Hn + h)) * Tn) * Dn];
    const float* vbase = &vt[(((size_t)(b * Hn + h)) * Tn) * Dn];

    int ntiles = (qtile * 64 + 63) / TK + 1;
    for (int t0 = 0; t0 < ntiles; t0++) {
        int j0 = t0 * TK;
        __syncthreads();
        // cooperative load: TK*64 floats each => 8 float4 per thread per array
#pragma unroll
        for (int r = 0; r < 8; r++) {
            int lin = r * 64 + tid;      // float4 index 0..511
            int row = lin / 16;
            int c4 = lin % 16;
            ((float4*)Ks[row])[c4] = ((const float4*)&kbase[(size_t)(j0 + row) * Dn])[c4];
            ((float4*)Vs[row])[c4] = ((const float4*)&vbase[(size_t)(j0 + row) * Dn])[c4];
        }
        __syncthreads();

        int jmax = i - j0;
        if (jmax < 0) continue;            // this thread's row is before this key tile
        if (jmax > TK - 1) jmax = TK - 1;

        float s[TK];
        float mt = -1e30f;
#pragma unroll
        for (int j = 0; j < TK; j++) {
            float d0 = 0.f, d1 = 0.f, d2 = 0.f, d3 = 0.f;
#pragma unroll
            for (int d4 = 0; d4 < 16; d4++) {
                float4 kv = ((const float4*)Ks[j])[d4];
                d0 += q[d4].x * kv.x;
                d1 += q[d4].y * kv.y;
                d2 += q[d4].z * kv.z;
                d3 += q[d4].w * kv.w;
            }
            float dot = (d0 + d1) + (d2 + d3);
            float xx = fmaxf(dot, 1.f + 1e-7f);
            float dist = acoshf(xx);
            float sc = -dist * dist * 0.125f;        // 1/sqrt(64) = 0.125
            sc = (j <= jmax) ? sc : -1e30f;
            s[j] = sc;
            mt = fmaxf(mt, sc);
        }
        float mnew = fmaxf(m, mt);
        float scale = expf(m - mnew);
        l *= scale;
#pragma unroll
        for (int d = 0; d < 64; d++) acc[d] *= scale;
#pragma unroll
        for (int j = 0; j < TK; j++) {
            float p = expf(s[j] - mnew);
            l += p;
#pragma unroll
            for (int d4 = 0; d4 < 16; d4++) {
                float4 vv = ((const float4*)Vs[j])[d4];
                acc[d4 * 4 + 0] += p * vv.x;
                acc[d4 * 4 + 1] += p * vv.y;
                acc[d4 * 4 + 2] += p * vv.z;
                acc[d4 * 4 + 3] += p * vv.w;
            }
        }
        m = mnew;
    }

    float sp = spikes[b * Tn + i];
    float inv = sp / l;
    float* yrow = &y[((size_t)(b * Tn + i)) * Cn + h * Dn];
#pragma unroll
    for (int d4 = 0; d4 < 16; d4++) {
        float4 o;
        o.x = acc[d4 * 4 + 0] * inv;
        o.y = acc[d4 * 4 + 1] * inv;
        o.z = acc[d4 * 4 + 2] * inv;
        o.w = acc[d4 * 4 + 3] * inv;
        ((float4*)yrow)[d4] = o;
    }
}

// ---------------- launcher ----------------
extern "C" void kernel_launch(void* const* d_in, const int* in_sizes, int n_in,
                              void* d_out, int out_size) {
    const float* x    = (const float*)d_in[0];
    const float* Wqkv = (const float*)d_in[1];
    const float* bqkv = (const float*)d_in[2];
    const float* Wout = (const float*)d_in[3];
    const float* bout = (const float*)d_in[4];
    const float* wsur = (const float*)d_in[5];
    const float* bsur = (const float*)d_in[6];
    const float* thr  = (const float*)d_in[7];
    float* out = (float*)d_out;

    float *qkv, *qt, *kt, *vt, *spk, *y;
    cudaGetSymbolAddress((void**)&qkv, g_qkv);
    cudaGetSymbolAddress((void**)&qt, g_qt);
    cudaGetSymbolAddress((void**)&kt, g_kt);
    cudaGetSymbolAddress((void**)&vt, g_vt);
    cudaGetSymbolAddress((void**)&spk, g_spk);
    cudaGetSymbolAddress((void**)&y, g_y);

    // 1. spikes
    spike_kernel<<<Bn * Tn, 256>>>(x, wsur, bsur, thr, spk);
    // 2. qkv = x @ W_qkv + b_qkv   (4096 x 3072 x 1024)
    gemm_bias_kernel<<<dim3(3 * Cn / 64, Bn * Tn / 128), 256>>>(
        x, Wqkv, bqkv, qkv, Bn * Tn, 3 * Cn, Cn);
    // 3. hyperbolic transform + relayout
    transform_kernel<<<(Bn * Tn * Hn) / 8, 256>>>(qkv, qt, kt, vt);
    // 4. causal Lorentz attention with spike row-mask
    attn_kernel<<<dim3(Tn / 64, Hn, Bn), 64>>>(qt, kt, vt, spk, y);
    // 5. out = y @ W_out + b_out   (4096 x 1024 x 1024)
    gemm_bias_kernel<<<dim3(Cn / 64, Bn * Tn / 128), 256>>>(
        y, Wout, bout, out, Bn * Tn, Cn, Cn);
}

// round 4
// speedup vs baseline: 1.8955x; 1.8955x over previous
#include <cuda_runtime.h>
#include <cuda_bf16.h>
#include <math.h>
#include <stdint.h>

// Problem constants
#define Bn 4
#define Tn 1024
#define Cn 1024
#define Hn 16
#define Dn 64
#define MR (Bn*Tn)

// ---------------- scratch (no allocations allowed) ----------------
__device__ float g_qkv[MR * 3 * Cn];
__device__ float g_qt [Bn * Hn * Tn * Dn];
__device__ float g_kt [Bn * Hn * Tn * Dn];
__device__ float g_vt [Bn * Hn * Tn * Dn];
__device__ float g_spk[MR];
__device__ float g_y  [MR * Cn];
__device__ __nv_bfloat16 g_xh[MR * Cn], g_xl[MR * Cn];
__device__ __nv_bfloat16 g_yh[MR * Cn], g_yl[MR * Cn];
__device__ __nv_bfloat16 g_wqh[3 * Cn * Cn], g_wql[3 * Cn * Cn];   // W_qkv^T [3072][1024]
__device__ __nv_bfloat16 g_woh[Cn * Cn], g_wol[Cn * Cn];           // W_out^T [1024][1024]

// ---------------- helpers ----------------
__device__ __forceinline__ uint32_t smem_u32(const void* p) {
    uint32_t a;
    asm("{ .reg .u64 t; cvta.to.shared.u64 t, %1; cvt.u32.u64 %0, t; }" : "=r"(a) : "l"(p));
    return a;
}
__device__ __forceinline__ void cp16(uint32_t dst, const void* src) {
    asm volatile("cp.async.cg.shared.global [%0], [%1], 16;" :: "r"(dst), "l"(src));
}
__device__ __forceinline__ void cp_commit() {
    asm volatile("cp.async.commit_group;" ::: "memory");
}
template <int N>
__device__ __forceinline__ void cp_wait() {
    asm volatile("cp.async.wait_group %0;" :: "n"(N) : "memory");
}
__device__ __forceinline__ void mma16816(float* d, const uint32_t* a, const uint32_t* b) {
    asm volatile(
        "mma.sync.aligned.m16n8k16.row.col.f32.bf16.bf16.f32 "
        "{%0,%1,%2,%3}, {%4,%5,%6,%7}, {%8,%9}, {%0,%1,%2,%3};"
        : "+f"(d[0]), "+f"(d[1]), "+f"(d[2]), "+f"(d[3])
        : "r"(a[0]), "r"(a[1]), "r"(a[2]), "r"(a[3]), "r"(b[0]), "r"(b[1]));
}

// ---------------- fast math (FMA-pipe log/exp, Cephes coefficients) ----------------
__device__ __forceinline__ float fast_log(float a) {   // a >= 1
    int i = __float_as_int(a);
    int e = (i >> 23) - 126;
    float m = __int_as_float((i & 0x007FFFFF) | 0x3F000000);
    if (m < 0.70710678118f) { m = m + m; e -= 1; }
    float x = m - 1.0f;
    float z = x * x;
    float y = 7.0376836292e-2f;
    y = fmaf(y, x, -1.1514610310e-1f);
    y = fmaf(y, x,  1.1676998740e-1f);
    y = fmaf(y, x, -1.2420140846e-1f);
    y = fmaf(y, x,  1.4249322787e-1f);
    y = fmaf(y, x, -1.6668057665e-1f);
    y = fmaf(y, x,  2.0000714765e-1f);
    y = fmaf(y, x, -2.4999993993e-1f);
    y = fmaf(y, x,  3.3333331174e-1f);
    y = y * x * z;
    float ef = (float)e;
    y = fmaf(ef, -2.12194440e-4f, y);
    y = fmaf(-0.5f, z, y);
    float r = x + y;
    return fmaf(ef, 0.693359375f, r);
}
__device__ __forceinline__ float fast_exp_neg(float zin) {  // zin <= 0
    float z = fmaxf(zin, -80.f);
    float fn = fmaf(z, 1.44269504089f, 12582912.f);
    int n = __float_as_int(fn) - 0x4B400000;
    float nf = fn - 12582912.f;
    float r = fmaf(nf, -0.693359375f, z);
    r = fmaf(nf, 2.12194440e-4f, r);
    float y = 1.9875691500e-4f;
    y = fmaf(y, r, 1.3981999507e-3f);
    y = fmaf(y, r, 8.3334519073e-3f);
    y = fmaf(y, r, 4.1665795894e-2f);
    y = fmaf(y, r, 1.6666665459e-1f);
    y = fmaf(y, r, 5.0000001201e-1f);
    float res = fmaf(y * r, r, r) + 1.0f;
    return res * __int_as_float((n + 127) << 23);
}

// ---------------- spike / surrogate ----------------
__global__ void spike_kernel(const float* __restrict__ x, const float* __restrict__ w_sur,
                             const float* __restrict__ b_sur, const float* __restrict__ threshold,
                             float* __restrict__ spikes) {
    __shared__ float red[256];
    int bt = blockIdx.x;
    const float* xr = &x[(size_t)bt * Cn];
    float s = 0.f;
    for (int c = threadIdx.x; c < Cn; c += 256) s += xr[c] * w_sur[c];
    red[threadIdx.x] = s;
    __syncthreads();
    for (int o = 128; o; o >>= 1) {
        if (threadIdx.x < o) red[threadIdx.x] += red[threadIdx.x + o];
        __syncthreads();
    }
    if (threadIdx.x == 0) {
        float imp = 1.f / (1.f + expf(-(red[0] + b_sur[0])));
        spikes[bt] = imp > threshold[0] ? 1.f : 0.f;
    }
}

// ---------------- fp32 -> bf16 hi/lo converters ----------------
__global__ void conv_rows_kernel(const float* __restrict__ A,
                                 __nv_bfloat16* __restrict__ h, __nv_bfloat16* __restrict__ l) {
    int i = blockIdx.x * 256 + threadIdx.x;
    float v = A[i];
    __nv_bfloat16 hh = __float2bfloat16(v);
    h[i] = hh;
    l[i] = __float2bfloat16(v - __bfloat162float(hh));
}
// W [K][N] fp32 -> W^T [N][K] bf16 hi/lo
__global__ void convT_kernel(const float* __restrict__ W,
                             __nv_bfloat16* __restrict__ th, __nv_bfloat16* __restrict__ tl,
                             int K, int N) {
    __shared__ float t[32][33];
    int n0 = blockIdx.x * 32, k0 = blockIdx.y * 32;
    for (int i = threadIdx.y; i < 32; i += 8)
        t[i][threadIdx.x] = W[(size_t)(k0 + i) * N + n0 + threadIdx.x];
    __syncthreads();
    for (int i = threadIdx.y; i < 32; i += 8) {
        float v = t[threadIdx.x][i];
        __nv_bfloat16 hh = __float2bfloat16(v);
        size_t o = (size_t)(n0 + i) * K + k0 + threadIdx.x;
        th[o] = hh;
        tl[o] = __float2bfloat16(v - __bfloat162float(hh));
    }
}

// ---------------- mma.sync split-bf16 GEMM: C[M][N] = A @ B^T + bias ----------------
// A: [M][K] hi/lo bf16; B: [N][K] hi/lo bf16. Tiles: BM=128, BN=128, BK=32.
// 8 warps (4 M x 2 N), warp tile 32x64. Smem K-stride padded to 40 elems (80B).
#define BKc 32
#define PADK 40
#define AH_OFF 0
#define AL_OFF 10240
#define BH_OFF 20480
#define BL_OFF 30720
#define STAGE_B 40960
#define GEMM_SMEM (2 * STAGE_B)

__global__ __launch_bounds__(256) void mma_gemm_kernel(
    const __nv_bfloat16* __restrict__ Ah, const __nv_bfloat16* __restrict__ Al,
    const __nv_bfloat16* __restrict__ Bh, const __nv_bfloat16* __restrict__ Bl,
    const float* __restrict__ bias, float* __restrict__ Cm, int N, int K) {
    extern __shared__ __align__(128) char smem[];
    uint32_t sb = smem_u32(smem);

    int tid = threadIdx.x;
    int lane = tid & 31;
    int w = tid >> 5;
    int wm = w & 3;          // 0..3  (M subtile of 32)
    int wn = w >> 2;         // 0..1  (N subtile of 64)
    int bm = blockIdx.y * 128;
    int bn = blockIdx.x * 128;

    // global load coords: lin in [0,512): r = lin/4 (row), c = lin%4 (16B chunk)
    int lin0 = tid;            // A rows 0..63  handled it=0, 64..127 it=1
    // smem byte offset for (r,c): r*80 + c*16

    float acc[2][8][4];
#pragma unroll
    for (int mt = 0; mt < 2; mt++)
#pragma unroll
        for (int nt = 0; nt < 8; nt++)
#pragma unroll
            for (int q = 0; q < 4; q++) acc[mt][nt][q] = 0.f;

    int NK = K / BKc;

    // ---- stage loader ----
    auto load_stage = [&](int kc, int s) {
        uint32_t base = sb + s * STAGE_B;
        int k0 = kc * BKc;
#pragma unroll
        for (int it = 0; it < 2; it++) {
            int lin = it * 256 + lin0;        // 0..511
            int r = lin >> 2, c = lin & 3;
            uint32_t so = (uint32_t)(r * 80 + c * 16);
            size_t go = (size_t)(bm + r) * K + k0 + c * 8;
            cp16(base + AH_OFF + so, Ah + go);
            cp16(base + AL_OFF + so, Al + go);
        }
#pragma unroll
        for (int it = 0; it < 2; it++) {
            int lin = it * 256 + lin0;
            int r = lin >> 2, c = lin & 3;
            uint32_t so = (uint32_t)(r * 80 + c * 16);
            size_t go = (size_t)(bn + r) * K + k0 + c * 8;
            cp16(base + BH_OFF + so, Bh + go);
            cp16(base + BL_OFF + so, Bl + go);
        }
        cp_commit();
    };

    load_stage(0, 0);

    int arow = wm * 32 + (lane >> 2);       // +mt*16, +8 for hi rows
    int kcol = 2 * (lane & 3);              // element col within k16
    int brow = wn * 64 + (lane >> 2);       // +nt*8

    for (int kc = 0; kc < NK; kc++) {
        if (kc + 1 < NK) load_stage(kc + 1, (kc + 1) & 1);
        if (kc + 1 < NK) cp_wait<1>(); else cp_wait<0>();
        __syncthreads();

        uint32_t base = sb + (kc & 1) * STAGE_B;
        const char* sm = (const char*)smem + (kc & 1) * STAGE_B;

#pragma unroll
        for (int ks = 0; ks < 2; ks++) {     // two k16 steps
            int kb = (ks * 16 + kcol) * 2;   // byte col
            uint32_t ah[2][4], al[2][4];
#pragma unroll
            for (int mt = 0; mt < 2; mt++) {
                int r0 = (arow + mt * 16) * 80 + kb;
                ah[mt][0] = *(const uint32_t*)(sm + AH_OFF + r0);
                ah[mt][1] = *(const uint32_t*)(sm + AH_OFF + r0 + 8 * 80);
                ah[mt][2] = *(const uint32_t*)(sm + AH_OFF + r0 + 16);
                ah[mt][3] = *(const uint32_t*)(sm + AH_OFF + r0 + 8 * 80 + 16);
                al[mt][0] = *(const uint32_t*)(sm + AL_OFF + r0);
                al[mt][1] = *(const uint32_t*)(sm + AL_OFF + r0 + 8 * 80);
                al[mt][2] = *(const uint32_t*)(sm + AL_OFF + r0 + 16);
                al[mt][3] = *(const uint32_t*)(sm + AL_OFF + r0 + 8 * 80 + 16);
            }
#pragma unroll
            for (int nt = 0; nt < 8; nt++) {
                int r0 = (brow + nt * 8) * 80 + kb;
                uint32_t bh[2], bl[2];
                bh[0] = *(const uint32_t*)(sm + BH_OFF + r0);
                bh[1] = *(const uint32_t*)(sm + BH_OFF + r0 + 16);
                bl[0] = *(const uint32_t*)(sm + BL_OFF + r0);
                bl[1] = *(const uint32_t*)(sm + BL_OFF + r0 + 16);
#pragma unroll
                for (int mt = 0; mt < 2; mt++) {
                    mma16816(acc[mt][nt], ah[mt], bh);
                    mma16816(acc[mt][nt], ah[mt], bl);
                    mma16816(acc[mt][nt], al[mt], bh);
                }
            }
        }
        __syncthreads();
    }

    // epilogue
#pragma unroll
    for (int mt = 0; mt < 2; mt++) {
        int m0 = bm + wm * 32 + mt * 16 + (lane >> 2);
#pragma unroll
        for (int nt = 0; nt < 8; nt++) {
            int c0 = bn + wn * 64 + nt * 8 + 2 * (lane & 3);
            float b0 = bias[c0], b1 = bias[c0 + 1];
            float* p0 = Cm + (size_t)m0 * N + c0;
            p0[0] = acc[mt][nt][0] + b0;
            p0[1] = acc[mt][nt][1] + b1;
            float* p1 = p0 + 8 * (size_t)N;
            p1[0] = acc[mt][nt][2] + b0;
            p1[1] = acc[mt][nt][3] + b1;
        }
    }
}

// ---------------- expmap0 transform ----------------
__global__ void transform_kernel(const float* __restrict__ qkv,
                                 float* __restrict__ qt, float* __restrict__ kt,
                                 float* __restrict__ vt) {
    int gw = (blockIdx.x * blockDim.x + threadIdx.x) >> 5;
    int lane = threadIdx.x & 31;
    int bt = gw / Hn;
    int h = gw % Hn;
    int b = bt / Tn;
    int t = bt % Tn;

    const float* base = &qkv[(size_t)bt * (3 * Cn) + h * Dn];
    float2 uq = ((const float2*)base)[lane];
    float2 uk = ((const float2*)(base + Cn))[lane];
    float2 uv = ((const float2*)(base + 2 * Cn))[lane];

    float sq = uq.y * uq.y + (lane ? uq.x * uq.x : 0.f);
    float sk = uk.y * uk.y + (lane ? uk.x * uk.x : 0.f);
#pragma unroll
    for (int off = 16; off; off >>= 1) {
        sq += __shfl_xor_sync(0xFFFFFFFFu, sq, off);
        sk += __shfl_xor_sync(0xFFFFFFFFu, sk, off);
    }
    float u0q = __shfl_sync(0xFFFFFFFFu, uq.x, 0);
    float u0k = __shfl_sync(0xFFFFFFFFu, uk.x, 0);

    float nq = sqrtf(fmaxf(sq - u0q * u0q, 1e-8f));
    float nk = sqrtf(fmaxf(sk - u0k * u0k, 1e-8f));
    float fq = sinhf(nq) / nq;
    float fk = sinhf(nk) / nk;
    float tmq = coshf(nq);
    float tmk = coshf(nk);

    size_t out = (((size_t)(b * Hn + h)) * Tn + t) * Dn;
    float2 oq, ok;
    oq.x = lane ? fq * uq.x : tmq;
    oq.y = fq * uq.y;
    ok.x = lane ? -fk * uk.x : tmk;
    ok.y = -fk * uk.y;
    ((float2*)&qt[out])[lane] = oq;
    ((float2*)&kt[out])[lane] = ok;
    ((float2*)&vt[out])[lane] = uv;
}

// ---------------- causal Lorentz attention (no-max softmax, FMA-pipe math) ----------------
#define TK 32
__global__ __launch_bounds__(64) void attn_kernel(
    const float* __restrict__ qt, const float* __restrict__ kt,
    const float* __restrict__ vt, const float* __restrict__ spikes,
    float* __restrict__ y) {
    __shared__ float Ks[TK][Dn];
    __shared__ float Vs[TK][Dn];

    int tid = threadIdx.x;
    int qtile = gridDim.x - 1 - blockIdx.x;   // longest tiles first
    int h = blockIdx.y;
    int b = blockIdx.z;
    int i = qtile * 64 + tid;

    const float* qrow = &qt[(((size_t)(b * Hn + h)) * Tn + i) * Dn];
    float4 q[16];
#pragma unroll
    for (int d4 = 0; d4 < 16; d4++) q[d4] = ((const float4*)qrow)[d4];

    float acc[64];
#pragma unroll
    for (int d = 0; d < 64; d++) acc[d] = 0.f;
    float l = 0.f;

    const float* kbase = &kt[(((size_t)(b * Hn + h)) * Tn) * Dn];
    const float* vbase = &vt[(((size_t)(b * Hn + h)) * Tn) * Dn];

    int ntiles = (qtile * 64 + 63) / TK + 1;
    for (int t0 = 0; t0 < ntiles; t0++) {
        int j0 = t0 * TK;
        __syncthreads();
#pragma unroll
        for (int r = 0; r < 8; r++) {
            int lin = r * 64 + tid;
            int row = lin / 16;
            int c4 = lin % 16;
            ((float4*)Ks[row])[c4] = ((const float4*)&kbase[(size_t)(j0 + row) * Dn])[c4];
            ((float4*)Vs[row])[c4] = ((const float4*)&vbase[(size_t)(j0 + row) * Dn])[c4];
        }
        __syncthreads();

        int jmax = i - j0;
        if (jmax < 0) continue;
#pragma unroll
        for (int j = 0; j < TK; j++) {
            float d0 = 0.f, d1 = 0.f, d2 = 0.f, d3 = 0.f;
#pragma unroll
            for (int d4 = 0; d4 < 16; d4++) {
                float4 kv = ((const float4*)Ks[j])[d4];
                d0 = fmaf(q[d4].x, kv.x, d0);
                d1 = fmaf(q[d4].y, kv.y, d1);
                d2 = fmaf(q[d4].z, kv.z, d2);
                d3 = fmaf(q[d4].w, kv.w, d3);
            }
            float dot = (d0 + d1) + (d2 + d3);
            float xx = fmaxf(dot, 1.0000001f);
            float s2 = fmaf(xx, xx, -1.f);
            float sq;
            asm("sqrt.approx.f32 %0, %1;" : "=f"(sq) : "f"(s2));
            float dist = fast_log(xx + sq);
            float p = fast_exp_neg(dist * dist * -0.125f);
            p = (j <= jmax) ? p : 0.f;
            l += p;
#pragma unroll
            for (int d4 = 0; d4 < 16; d4++) {
                float4 vv = ((const float4*)Vs[j])[d4];
                acc[d4 * 4 + 0] = fmaf(p, vv.x, acc[d4 * 4 + 0]);
                acc[d4 * 4 + 1] = fmaf(p, vv.y, acc[d4 * 4 + 1]);
                acc[d4 * 4 + 2] = fmaf(p, vv.z, acc[d4 * 4 + 2]);
                acc[d4 * 4 + 3] = fmaf(p, vv.w, acc[d4 * 4 + 3]);
            }
        }
    }

    float sp = spikes[b * Tn + i];
    float inv = sp / l;
    float* yrow = &y[((size_t)(b * Tn + i)) * Cn + h * Dn];
#pragma unroll
    for (int d4 = 0; d4 < 16; d4++) {
        float4 o;
        o.x = acc[d4 * 4 + 0] * inv;
        o.y = acc[d4 * 4 + 1] * inv;
        o.z = acc[d4 * 4 + 2] * inv;
        o.w = acc[d4 * 4 + 3] * inv;
        ((float4*)yrow)[d4] = o;
    }
}

// ---------------- launcher ----------------
extern "C" void kernel_launch(void* const* d_in, const int* in_sizes, int n_in,
                              void* d_out, int out_size) {
    const float* x    = (const float*)d_in[0];
    const float* Wqkv = (const float*)d_in[1];
    const float* bqkv = (const float*)d_in[2];
    const float* Wout = (const float*)d_in[3];
    const float* bout = (const float*)d_in[4];
    const float* wsur = (const float*)d_in[5];
    const float* bsur = (const float*)d_in[6];
    const float* thr  = (const float*)d_in[7];
    float* out = (float*)d_out;

    float *qkv, *qt, *kt, *vt, *spk, *y;
    __nv_bfloat16 *xh, *xl, *yh, *yl, *wqh, *wql, *woh, *wol;
    cudaGetSymbolAddress((void**)&qkv, g_qkv);
    cudaGetSymbolAddress((void**)&qt, g_qt);
    cudaGetSymbolAddress((void**)&kt, g_kt);
    cudaGetSymbolAddress((void**)&vt, g_vt);
    cudaGetSymbolAddress((void**)&spk, g_spk);
    cudaGetSymbolAddress((void**)&y, g_y);
    cudaGetSymbolAddress((void**)&xh, g_xh);
    cudaGetSymbolAddress((void**)&xl, g_xl);
    cudaGetSymbolAddress((void**)&yh, g_yh);
    cudaGetSymbolAddress((void**)&yl, g_yl);
    cudaGetSymbolAddress((void**)&wqh, g_wqh);
    cudaGetSymbolAddress((void**)&wql, g_wql);
    cudaGetSymbolAddress((void**)&woh, g_woh);
    cudaGetSymbolAddress((void**)&wol, g_wol);

    cudaFuncSetAttribute(mma_gemm_kernel, cudaFuncAttributeMaxDynamicSharedMemorySize, GEMM_SMEM);

    // 1. spikes
    spike_kernel<<<MR, 256>>>(x, wsur, bsur, thr, spk);
    // 2. split-bf16 conversions
    conv_rows_kernel<<<(MR * Cn) / 256, 256>>>(x, xh, xl);
    convT_kernel<<<dim3(3 * Cn / 32, Cn / 32), dim3(32, 8)>>>(Wqkv, wqh, wql, Cn, 3 * Cn);
    // 3. qkv = x @ W_qkv + b  (M=4096, N=3072, K=1024)
    mma_gemm_kernel<<<dim3(3 * Cn / 128, MR / 128), 256, GEMM_SMEM>>>(
        xh, xl, wqh, wql, bqkv, qkv, 3 * Cn, Cn);
    // 4. hyperbolic transform + relayout
    transform_kernel<<<(MR * Hn) / 8, 256>>>(qkv, qt, kt, vt);
    // 5. attention
    attn_kernel<<<dim3(Tn / 64, Hn, Bn), 64>>>(qt, kt, vt, spk, y);
    // 6. out projection
    conv_rows_kernel<<<(MR * Cn) / 256, 256>>>(y, yh, yl);
    convT_kernel<<<dim3(Cn / 32, Cn / 32), dim3(32, 8)>>>(Wout, woh, wol, Cn, Cn);
    mma_gemm_kernel<<<dim3(Cn / 128, MR / 128), 256, GEMM_SMEM>>>(
        yh, yl, woh, wol, bout, out, Cn, Cn);
}

// round 6
// speedup vs baseline: 3.1409x; 1.6570x over previous
#include <cuda_runtime.h>
#include <cuda_bf16.h>
#include <math.h>
#include <stdint.h>

// Problem constants
#define Bn 4
#define Tn 1024
#define Cn 1024
#define Hn 16
#define Dn 64
#define MR (Bn*Tn)
#define BH (Bn*Hn)

// ---------------- scratch (no allocations allowed) ----------------
__device__ float g_qkv[MR * 3 * Cn];
__device__ float g_spk[MR];
__device__ float g_y  [MR * Cn];
__device__ __nv_bfloat16 g_xh[MR * Cn], g_xl[MR * Cn];
__device__ __nv_bfloat16 g_yh[MR * Cn], g_yl[MR * Cn];
__device__ __nv_bfloat16 g_wqh[3 * Cn * Cn], g_wql[3 * Cn * Cn];
__device__ __nv_bfloat16 g_woh[Cn * Cn], g_wol[Cn * Cn];
// attention operands: [bh][t][d] for q,k; [bh][d][t] for v^T
__device__ __nv_bfloat16 g_qth[BH * Tn * Dn], g_qtl[BH * Tn * Dn];
__device__ __nv_bfloat16 g_kth[BH * Tn * Dn], g_ktl[BH * Tn * Dn];
__device__ __nv_bfloat16 g_vth[BH * Dn * Tn], g_vtl[BH * Dn * Tn];

// ---------------- helpers ----------------
__device__ __forceinline__ uint32_t smem_u32(const void* p) {
    uint32_t a;
    asm("{ .reg .u64 t; cvta.to.shared.u64 t, %1; cvt.u32.u64 %0, t; }" : "=r"(a) : "l"(p));
    return a;
}
__device__ __forceinline__ void cp16(uint32_t dst, const void* src) {
    asm volatile("cp.async.cg.shared.global [%0], [%1], 16;" :: "r"(dst), "l"(src));
}
__device__ __forceinline__ void cp_commit() {
    asm volatile("cp.async.commit_group;" ::: "memory");
}
template <int N>
__device__ __forceinline__ void cp_wait() {
    asm volatile("cp.async.wait_group %0;" :: "n"(N) : "memory");
}
__device__ __forceinline__ void mma16816(float* d, const uint32_t* a, const uint32_t* b) {
    asm volatile(
        "mma.sync.aligned.m16n8k16.row.col.f32.bf16.bf16.f32 "
        "{%0,%1,%2,%3}, {%4,%5,%6,%7}, {%8,%9}, {%0,%1,%2,%3};"
        : "+f"(d[0]), "+f"(d[1]), "+f"(d[2]), "+f"(d[3])
        : "r"(a[0]), "r"(a[1]), "r"(a[2]), "r"(a[3]), "r"(b[0]), "r"(b[1]));
}
__device__ __forceinline__ uint32_t pack_bf16x2(float hi, float lo) {
    uint32_t r;
    asm("cvt.rn.bf16x2.f32 %0, %1, %2;" : "=r"(r) : "f"(hi), "f"(lo));
    return r;
}

// ---------------- fast math (FMA-pipe log/exp) ----------------
__device__ __forceinline__ float fast_log(float a) {   // a >= 1
    int i = __float_as_int(a);
    int e = (i >> 23) - 126;
    float m = __int_as_float((i & 0x007FFFFF) | 0x3F000000);
    if (m < 0.70710678118f) { m = m + m; e -= 1; }
    float x = m - 1.0f;
    float z = x * x;
    float y = 7.0376836292e-2f;
    y = fmaf(y, x, -1.1514610310e-1f);
    y = fmaf(y, x,  1.1676998740e-1f);
    y = fmaf(y, x, -1.2420140846e-1f);
    y = fmaf(y, x,  1.4249322787e-1f);
    y = fmaf(y, x, -1.6668057665e-1f);
    y = fmaf(y, x,  2.0000714765e-1f);
    y = fmaf(y, x, -2.4999993993e-1f);
    y = fmaf(y, x,  3.3333331174e-1f);
    y = y * x * z;
    float ef = (float)e;
    y = fmaf(ef, -2.12194440e-4f, y);
    y = fmaf(-0.5f, z, y);
    float r = x + y;
    return fmaf(ef, 0.693359375f, r);
}
__device__ __forceinline__ float fast_exp_neg(float zin) {  // zin <= 0
    float z = fmaxf(zin, -80.f);
    float fn = fmaf(z, 1.44269504089f, 12582912.f);
    int n = __float_as_int(fn) - 0x4B400000;
    float nf = fn - 12582912.f;
    float r = fmaf(nf, -0.693359375f, z);
    r = fmaf(nf, 2.12194440e-4f, r);
    float y = 1.9875691500e-4f;
    y = fmaf(y, r, 1.3981999507e-3f);
    y = fmaf(y, r, 8.3334519073e-3f);
    y = fmaf(y, r, 4.1665795894e-2f);
    y = fmaf(y, r, 1.6666665459e-1f);
    y = fmaf(y, r, 5.0000001201e-1f);
    float res = fmaf(y * r, r, r) + 1.0f;
    return res * __int_as_float((n + 127) << 23);
}
__device__ __forceinline__ float score_p(float x) {
    float xx = fmaxf(x, 1.0000001f);
    float s2 = fmaf(xx, xx, -1.f);
    float sq;
    asm("sqrt.approx.f32 %0, %1;" : "=f"(sq) : "f"(s2));
    float dist = fast_log(xx + sq);
    return fast_exp_neg(dist * dist * -0.125f);
}

// ---------------- spike / surrogate ----------------
__global__ void spike_kernel(const float* __restrict__ x, const float* __restrict__ w_sur,
                             const float* __restrict__ b_sur, const float* __restrict__ threshold,
                             float* __restrict__ spikes) {
    __shared__ float red[256];
    int bt = blockIdx.x;
    const float* xr = &x[(size_t)bt * Cn];
    float s = 0.f;
    for (int c = threadIdx.x; c < Cn; c += 256) s += xr[c] * w_sur[c];
    red[threadIdx.x] = s;
    __syncthreads();
    for (int o = 128; o; o >>= 1) {
        if (threadIdx.x < o) red[threadIdx.x] += red[threadIdx.x + o];
        __syncthreads();
    }
    if (threadIdx.x == 0) {
        float imp = 1.f / (1.f + expf(-(red[0] + b_sur[0])));
        spikes[bt] = imp > threshold[0] ? 1.f : 0.f;
    }
}

// ---------------- fp32 -> bf16 hi/lo converters ----------------
__global__ void conv_rows_kernel(const float* __restrict__ A,
                                 __nv_bfloat16* __restrict__ h, __nv_bfloat16* __restrict__ l) {
    int i = blockIdx.x * 256 + threadIdx.x;
    float v = A[i];
    __nv_bfloat16 hh = __float2bfloat16(v);
    h[i] = hh;
    l[i] = __float2bfloat16(v - __bfloat162float(hh));
}
__global__ void convT_kernel(const float* __restrict__ W,
                             __nv_bfloat16* __restrict__ th, __nv_bfloat16* __restrict__ tl,
                             int K, int N) {
    __shared__ float t[32][33];
    int n0 = blockIdx.x * 32, k0 = blockIdx.y * 32;
    for (int i = threadIdx.y; i < 32; i += 8)
        t[i][threadIdx.x] = W[(size_t)(k0 + i) * N + n0 + threadIdx.x];
    __syncthreads();
    for (int i = threadIdx.y; i < 32; i += 8) {
        float v = t[threadIdx.x][i];
        __nv_bfloat16 hh = __float2bfloat16(v);
        size_t o = (size_t)(n0 + i) * K + k0 + threadIdx.x;
        th[o] = hh;
        tl[o] = __float2bfloat16(v - __bfloat162float(hh));
    }
}

// ---------------- mma.sync split-bf16 GEMM (unchanged from R4) ----------------
#define AH_OFF 0
#define AL_OFF 10240
#define BH_OFF 20480
#define BL_OFF 30720
#define STAGE_B 40960
#define GEMM_SMEM (2 * STAGE_B)

__global__ __launch_bounds__(256) void mma_gemm_kernel(
    const __nv_bfloat16* __restrict__ Ah, const __nv_bfloat16* __restrict__ Al,
    const __nv_bfloat16* __restrict__ Bh, const __nv_bfloat16* __restrict__ Bl,
    const float* __restrict__ bias, float* __restrict__ Cm, int N, int K) {
    extern __shared__ __align__(128) char smem[];
    uint32_t sb = smem_u32(smem);

    int tid = threadIdx.x;
    int lane = tid & 31;
    int w = tid >> 5;
    int wm = w & 3;
    int wn = w >> 2;
    int bm = blockIdx.y * 128;
    int bn = blockIdx.x * 128;

    float acc[2][8][4];
#pragma unroll
    for (int mt = 0; mt < 2; mt++)
#pragma unroll
        for (int nt = 0; nt < 8; nt++)
#pragma unroll
            for (int q = 0; q < 4; q++) acc[mt][nt][q] = 0.f;

    int NK = K / 32;

    auto load_stage = [&](int kc, int s) {
        uint32_t base = sb + s * STAGE_B;
        int k0 = kc * 32;
#pragma unroll
        for (int it = 0; it < 2; it++) {
            int lin = it * 256 + tid;
            int r = lin >> 2, c = lin & 3;
            uint32_t so = (uint32_t)(r * 80 + c * 16);
            size_t go = (size_t)(bm + r) * K + k0 + c * 8;
            cp16(base + AH_OFF + so, Ah + go);
            cp16(base + AL_OFF + so, Al + go);
        }
#pragma unroll
        for (int it = 0; it < 2; it++) {
            int lin = it * 256 + tid;
            int r = lin >> 2, c = lin & 3;
            uint32_t so = (uint32_t)(r * 80 + c * 16);
            size_t go = (size_t)(bn + r) * K + k0 + c * 8;
            cp16(base + BH_OFF + so, Bh + go);
            cp16(base + BL_OFF + so, Bl + go);
        }
        cp_commit();
    };

    load_stage(0, 0);

    int arow = wm * 32 + (lane >> 2);
    int kcol = 2 * (lane & 3);
    int brow = wn * 64 + (lane >> 2);

    for (int kc = 0; kc < NK; kc++) {
        if (kc + 1 < NK) { load_stage(kc + 1, (kc + 1) & 1); cp_wait<1>(); }
        else cp_wait<0>();
        __syncthreads();

        const char* sm = (const char*)smem + (kc & 1) * STAGE_B;

#pragma unroll
        for (int ks = 0; ks < 2; ks++) {
            int kb = (ks * 16 + kcol) * 2;
            uint32_t ah[2][4], al[2][4];
#pragma unroll
            for (int mt = 0; mt < 2; mt++) {
                int r0 = (arow + mt * 16) * 80 + kb;
                ah[mt][0] = *(const uint32_t*)(sm + AH_OFF + r0);
                ah[mt][1] = *(const uint32_t*)(sm + AH_OFF + r0 + 8 * 80);
                ah[mt][2] = *(const uint32_t*)(sm + AH_OFF + r0 + 16);
                ah[mt][3] = *(const uint32_t*)(sm + AH_OFF + r0 + 8 * 80 + 16);
                al[mt][0] = *(const uint32_t*)(sm + AL_OFF + r0);
                al[mt][1] = *(const uint32_t*)(sm + AL_OFF + r0 + 8 * 80);
                al[mt][2] = *(const uint32_t*)(sm + AL_OFF + r0 + 16);
                al[mt][3] = *(const uint32_t*)(sm + AL_OFF + r0 + 8 * 80 + 16);
            }
#pragma unroll
            for (int nt = 0; nt < 8; nt++) {
                int r0 = (brow + nt * 8) * 80 + kb;
                uint32_t bh[2], bl[2];
                bh[0] = *(const uint32_t*)(sm + BH_OFF + r0);
                bh[1] = *(const uint32_t*)(sm + BH_OFF + r0 + 16);
                bl[0] = *(const uint32_t*)(sm + BL_OFF + r0);
                bl[1] = *(const uint32_t*)(sm + BL_OFF + r0 + 16);
#pragma unroll
                for (int mt = 0; mt < 2; mt++) {
                    mma16816(acc[mt][nt], ah[mt], bh);
                    mma16816(acc[mt][nt], ah[mt], bl);
                    mma16816(acc[mt][nt], al[mt], bh);
                }
            }
        }
        __syncthreads();
    }

#pragma unroll
    for (int mt = 0; mt < 2; mt++) {
        int m0 = bm + wm * 32 + mt * 16 + (lane >> 2);
#pragma unroll
        for (int nt = 0; nt < 8; nt++) {
            int c0 = bn + wn * 64 + nt * 8 + 2 * (lane & 3);
            float b0 = bias[c0], b1 = bias[c0 + 1];
            float* p0 = Cm + (size_t)m0 * N + c0;
            p0[0] = acc[mt][nt][0] + b0;
            p0[1] = acc[mt][nt][1] + b1;
            float* p1 = p0 + 8 * (size_t)N;
            p1[0] = acc[mt][nt][2] + b0;
            p1[1] = acc[mt][nt][3] + b1;
        }
    }
}

// ---------------- expmap0 transform -> split-bf16 q,k and v^T ----------------
__global__ void transform_kernel(const float* __restrict__ qkv,
                                 __nv_bfloat16* __restrict__ qth, __nv_bfloat16* __restrict__ qtl,
                                 __nv_bfloat16* __restrict__ kth, __nv_bfloat16* __restrict__ ktl,
                                 __nv_bfloat16* __restrict__ vth, __nv_bfloat16* __restrict__ vtl) {
    int gw = (blockIdx.x * blockDim.x + threadIdx.x) >> 5;
    int lane = threadIdx.x & 31;
    int bt = gw / Hn;
    int h = gw % Hn;
    int b = bt / Tn;
    int t = bt % Tn;
    int bh = b * Hn + h;

    const float* base = &qkv[(size_t)bt * (3 * Cn) + h * Dn];
    float2 uq = ((const float2*)base)[lane];
    float2 uk = ((const float2*)(base + Cn))[lane];
    float2 uv = ((const float2*)(base + 2 * Cn))[lane];

    float sq = uq.y * uq.y + (lane ? uq.x * uq.x : 0.f);
    float sk = uk.y * uk.y + (lane ? uk.x * uk.x : 0.f);
#pragma unroll
    for (int off = 16; off; off >>= 1) {
        sq += __shfl_xor_sync(0xFFFFFFFFu, sq, off);
        sk += __shfl_xor_sync(0xFFFFFFFFu, sk, off);
    }
    float u0q = __shfl_sync(0xFFFFFFFFu, uq.x, 0);
    float u0k = __shfl_sync(0xFFFFFFFFu, uk.x, 0);

    float nq = sqrtf(fmaxf(sq - u0q * u0q, 1e-8f));
    float nk = sqrtf(fmaxf(sk - u0k * u0k, 1e-8f));
    float fq = sinhf(nq) / nq;
    float fk = sinhf(nk) / nk;
    float tmq = coshf(nq);
    float tmk = coshf(nk);

    float2 oq, ok;
    oq.x = lane ? fq * uq.x : tmq;
    oq.y = fq * uq.y;
    ok.x = lane ? -fk * uk.x : tmk;
    ok.y = -fk * uk.y;

    size_t out = ((size_t)bh * Tn + t) * Dn;
    // q hi/lo
    __nv_bfloat16 qx = __float2bfloat16(oq.x), qy = __float2bfloat16(oq.y);
    ((__nv_bfloat162*)(qth + out))[lane] = __nv_bfloat162(qx, qy);
    ((__nv_bfloat162*)(qtl + out))[lane] = __nv_bfloat162(
        __float2bfloat16(oq.x - __bfloat162float(qx)), __float2bfloat16(oq.y - __bfloat162float(qy)));
    // k hi/lo
    __nv_bfloat16 kx = __float2bfloat16(ok.x), ky = __float2bfloat16(ok.y);
    ((__nv_bfloat162*)(kth + out))[lane] = __nv_bfloat162(kx, ky);
    ((__nv_bfloat162*)(ktl + out))[lane] = __nv_bfloat162(
        __float2bfloat16(ok.x - __bfloat162float(kx)), __float2bfloat16(ok.y - __bfloat162float(ky)));
    // v^T hi/lo: [bh][d][t]
    int d0 = 2 * lane;
    size_t vbase = ((size_t)bh * Dn + d0) * Tn + t;
    __nv_bfloat16 vx = __float2bfloat16(uv.x), vy = __float2bfloat16(uv.y);
    vth[vbase] = vx;
    vth[vbase + Tn] = vy;
    vtl[vbase] = __float2bfloat16(uv.x - __bfloat162float(vx));
    vtl[vbase + Tn] = __float2bfloat16(uv.y - __bfloat162float(vy));
}

// ---------------- flash attention on mma.sync ----------------
// q-tile 128 (8 warps x m16), k-tile 64; K/V^T double-buffered.
// smem stage: Kh[64][72] Kl[64][72] Vh[64][72] Vl[64][72] (bf16, 144B rows)
#define ATK_OFF 0
#define ATKL_OFF 9216
#define ATV_OFF 18432
#define ATVL_OFF 27648
#define ATSTG 36864
#define ATTN_SMEM (2 * ATSTG)

__global__ __launch_bounds__(256) void attn_mma_kernel(
    const __nv_bfloat16* __restrict__ qth, const __nv_bfloat16* __restrict__ qtl,
    const __nv_bfloat16* __restrict__ kth, const __nv_bfloat16* __restrict__ ktl,
    const __nv_bfloat16* __restrict__ vth, const __nv_bfloat16* __restrict__ vtl,
    const float* __restrict__ spikes, float* __restrict__ y) {
    extern __shared__ __align__(128) char smem[];
    uint32_t sb = smem_u32(smem);

    int tid = threadIdx.x;
    int lane = tid & 31;
    int w = tid >> 5;

    int idx = blockIdx.x;
    int qt = 7 - (idx >> 6);          // longest first
    int bh = idx & 63;
    int b = bh >> 4, h = bh & 15;
    int q0 = qt * 128;

    // ---- issue Q loads (into stage0 area: Qh at 0, Ql at 18432) ----
    size_t qoff = ((size_t)bh * Tn + q0) * Dn;
#pragma unroll
    for (int it = 0; it < 4; it++) {
        int lin = it * 256 + tid;      // 0..1023
        int r = lin >> 3, c = lin & 7;
        cp16(sb + (uint32_t)(r * 144 + c * 16), qth + qoff + r * 64 + c * 8);
        cp16(sb + 18432u + (uint32_t)(r * 144 + c * 16), qtl + qoff + r * 64 + c * 8);
    }
    cp_commit();

    // ---- K/V tile loader ----
    size_t kbase = (size_t)bh * Tn * Dn;
    size_t vbase = (size_t)bh * Dn * Tn;
    auto load_tile = [&](int t, int s) {
        uint32_t base = sb + s * ATSTG;
        int k0 = t * 64;
#pragma unroll
        for (int it = 0; it < 2; it++) {
            int lin = it * 256 + tid;   // 0..511
            int r = lin >> 3, c = lin & 7;
            uint32_t so = (uint32_t)(r * 144 + c * 16);
            cp16(base + ATK_OFF + so, kth + kbase + (size_t)(k0 + r) * 64 + c * 8);
            cp16(base + ATKL_OFF + so, ktl + kbase + (size_t)(k0 + r) * 64 + c * 8);
            cp16(base + ATV_OFF + so, vth + vbase + (size_t)r * Tn + k0 + c * 8);
            cp16(base + ATVL_OFF + so, vtl + vbase + (size_t)r * Tn + k0 + c * 8);
        }
        cp_commit();
    };

    load_tile(0, 1);                 // tile 0 -> stage 1

    cp_wait<1>();                    // Q done (tile0 may be pending)
    __syncthreads();

    // ---- read Q fragments ----
    int rowi = lane >> 2;            // 0..7
    int qrow = w * 16 + rowi;
    uint32_t qfh[4][4], qfl[4][4];
#pragma unroll
    for (int ks = 0; ks < 4; ks++) {
        int cb = (ks * 16 + 2 * (lane & 3)) * 2;
        const char* qs = smem;
        const char* qsl = smem + 18432;
        qfh[ks][0] = *(const uint32_t*)(qs + qrow * 144 + cb);
        qfh[ks][1] = *(const uint32_t*)(qs + (qrow + 8) * 144 + cb);
        qfh[ks][2] = *(const uint32_t*)(qs + qrow * 144 + cb + 16);
        qfh[ks][3] = *(const uint32_t*)(qs + (qrow + 8) * 144 + cb + 16);
        qfl[ks][0] = *(const uint32_t*)(qsl + qrow * 144 + cb);
        qfl[ks][1] = *(const uint32_t*)(qsl + (qrow + 8) * 144 + cb);
        qfl[ks][2] = *(const uint32_t*)(qsl + qrow * 144 + cb + 16);
        qfl[ks][3] = *(const uint32_t*)(qsl + (qrow + 8) * 144 + cb + 16);
    }
    __syncthreads();                 // Q area free for stage0 use

    float O[8][4];
#pragma unroll
    for (int nt = 0; nt < 8; nt++)
#pragma unroll
        for (int q = 0; q < 4; q++) O[nt][q] = 0.f;
    float l0 = 0.f, l1 = 0.f;

    int r0g = q0 + w * 16 + rowi;    // absolute query rows
    int r1g = r0g + 8;

    int ntiles = qt * 2 + 2;
    for (int t = 0; t < ntiles; t++) {
        if (t + 1 < ntiles) { load_tile(t + 1, t & 1); cp_wait<1>(); }
        else cp_wait<0>();
        __syncthreads();

        int s = (t + 1) & 1;
        const char* Khs = smem + s * ATSTG + ATK_OFF;
        const char* Kls = smem + s * ATSTG + ATKL_OFF;
        const char* Vhs = smem + s * ATSTG + ATV_OFF;
        const char* Vls = smem + s * ATSTG + ATVL_OFF;
        int k0 = t * 64;

        // ---- S = Q K^T (3-pass split) ----
        float S[8][4];
#pragma unroll
        for (int nt = 0; nt < 8; nt++)
#pragma unroll
            for (int q = 0; q < 4; q++) S[nt][q] = 0.f;
#pragma unroll
        for (int ks = 0; ks < 4; ks++) {
            int cb = (ks * 16 + 2 * (lane & 3)) * 2;
#pragma unroll
            for (int nt = 0; nt < 8; nt++) {
                int keyr = nt * 8 + rowi;
                uint32_t bhf[2], blf[2];
                bhf[0] = *(const uint32_t*)(Khs + keyr * 144 + cb);
                bhf[1] = *(const uint32_t*)(Khs + keyr * 144 + cb + 16);
                blf[0] = *(const uint32_t*)(Kls + keyr * 144 + cb);
                blf[1] = *(const uint32_t*)(Kls + keyr * 144 + cb + 16);
                mma16816(S[nt], qfh[ks], bhf);
                mma16816(S[nt], qfh[ks], blf);
                mma16816(S[nt], qfl[ks], bhf);
            }
        }

        // ---- transform scores -> p, pack to A-fragments ----
        uint32_t pha[4][4], pla[4][4];
#pragma unroll
        for (int nt = 0; nt < 8; nt++) {
            int jj0 = k0 + nt * 8 + 2 * (lane & 3);
            float p0 = score_p(S[nt][0]);
            float p1 = score_p(S[nt][1]);
            float p2 = score_p(S[nt][2]);
            float p3 = score_p(S[nt][3]);
            p0 = (jj0 <= r0g) ? p0 : 0.f;
            p1 = (jj0 + 1 <= r0g) ? p1 : 0.f;
            p2 = (jj0 <= r1g) ? p2 : 0.f;
            p3 = (jj0 + 1 <= r1g) ? p3 : 0.f;
            l0 += p0 + p1;
            l1 += p2 + p3;
            uint32_t h01 = pack_bf16x2(p1, p0);
            uint32_t h23 = pack_bf16x2(p3, p2);
            float f0 = __int_as_float(h01 << 16);
            float f1 = __int_as_float(h01 & 0xFFFF0000u);
            float f2 = __int_as_float(h23 << 16);
            float f3 = __int_as_float(h23 & 0xFFFF0000u);
            uint32_t l01 = pack_bf16x2(p1 - f1, p0 - f0);
            uint32_t l23 = pack_bf16x2(p3 - f3, p2 - f2);
            int js = nt >> 1, hf = nt & 1;
            pha[js][0 + 2 * hf] = h01;
            pha[js][1 + 2 * hf] = h23;
            pla[js][0 + 2 * hf] = l01;
            pla[js][1 + 2 * hf] = l23;
        }

        // ---- O += P V (3-pass split) ----
#pragma unroll
        for (int js = 0; js < 4; js++) {
            int kb = (js * 16 + 2 * (lane & 3)) * 2;
#pragma unroll
            for (int nt = 0; nt < 8; nt++) {
                int dimr = nt * 8 + rowi;
                uint32_t vhf[2], vlf[2];
                vhf[0] = *(const uint32_t*)(Vhs + dimr * 144 + kb);
                vhf[1] = *(const uint32_t*)(Vhs + dimr * 144 + kb + 16);
                vlf[0] = *(const uint32_t*)(Vls + dimr * 144 + kb);
                vlf[1] = *(const uint32_t*)(Vls + dimr * 144 + kb + 16);
                mma16816(O[nt], pha[js], vhf);
                mma16816(O[nt], pha[js], vlf);
                mma16816(O[nt], pla[js], vhf);
            }
        }
        __syncthreads();   // all warps done with stage s before it is refilled
    }

    // ---- row-sum reduction (4 lanes share a row) ----
    l0 += __shfl_xor_sync(0xFFFFFFFFu, l0, 1);
    l0 += __shfl_xor_sync(0xFFFFFFFFu, l0, 2);
    l1 += __shfl_xor_sync(0xFFFFFFFFu, l1, 1);
    l1 += __shfl_xor_sync(0xFFFFFFFFu, l1, 2);

    float inv0 = spikes[b * Tn + r0g] / l0;
    float inv1 = spikes[b * Tn + r1g] / l1;

    // ---- epilogue: y[b][t][h*64+col] ----
#pragma unroll
    for (int nt = 0; nt < 8; nt++) {
        int col = h * 64 + nt * 8 + 2 * (lane & 3);
        float2 o0 = make_float2(O[nt][0] * inv0, O[nt][1] * inv0);
        float2 o1 = make_float2(O[nt][2] * inv1, O[nt][3] * inv1);
        *(float2*)&y[((size_t)(b * Tn + r0g)) * Cn + col] = o0;
        *(float2*)&y[((size_t)(b * Tn + r1g)) * Cn + col] = o1;
    }
}

// ---------------- launcher ----------------
extern "C" void kernel_launch(void* const* d_in, const int* in_sizes, int n_in,
                              void* d_out, int out_size) {
    const float* x    = (const float*)d_in[0];
    const float* Wqkv = (const float*)d_in[1];
    const float* bqkv = (const float*)d_in[2];
    const float* Wout = (const float*)d_in[3];
    const float* bout = (const float*)d_in[4];
    const float* wsur = (const float*)d_in[5];
    const float* bsur = (const float*)d_in[6];
    const float* thr  = (const float*)d_in[7];
    float* out = (float*)d_out;

    float *qkv, *spk, *y;
    __nv_bfloat16 *xh, *xl, *yh, *yl, *wqh, *wql, *woh, *wol;
    __nv_bfloat16 *qth, *qtl, *kth, *ktl, *vth, *vtl;
    cudaGetSymbolAddress((void**)&qkv, g_qkv);
    cudaGetSymbolAddress((void**)&spk, g_spk);
    cudaGetSymbolAddress((void**)&y, g_y);
    cudaGetSymbolAddress((void**)&xh, g_xh);
    cudaGetSymbolAddress((void**)&xl, g_xl);
    cudaGetSymbolAddress((void**)&yh, g_yh);
    cudaGetSymbolAddress((void**)&yl, g_yl);
    cudaGetSymbolAddress((void**)&wqh, g_wqh);
    cudaGetSymbolAddress((void**)&wql, g_wql);
    cudaGetSymbolAddress((void**)&woh, g_woh);
    cudaGetSymbolAddress((void**)&wol, g_wol);
    cudaGetSymbolAddress((void**)&qth, g_qth);
    cudaGetSymbolAddress((void**)&qtl, g_qtl);
    cudaGetSymbolAddress((void**)&kth, g_kth);
    cudaGetSymbolAddress((void**)&ktl, g_ktl);
    cudaGetSymbolAddress((void**)&vth, g_vth);
    cudaGetSymbolAddress((void**)&vtl, g_vtl);

    cudaFuncSetAttribute(mma_gemm_kernel, cudaFuncAttributeMaxDynamicSharedMemorySize, GEMM_SMEM);
    cudaFuncSetAttribute(attn_mma_kernel, cudaFuncAttributeMaxDynamicSharedMemorySize, ATTN_SMEM);

    // 1. spikes
    spike_kernel<<<MR, 256>>>(x, wsur, bsur, thr, spk);
    // 2. split-bf16 conversions
    conv_rows_kernel<<<(MR * Cn) / 256, 256>>>(x, xh, xl);
    convT_kernel<<<dim3(3 * Cn / 32, Cn / 32), dim3(32, 8)>>>(Wqkv, wqh, wql, Cn, 3 * Cn);
    // 3. qkv = x @ W_qkv + b
    mma_gemm_kernel<<<dim3(3 * Cn / 128, MR / 128), 256, GEMM_SMEM>>>(
        xh, xl, wqh, wql, bqkv, qkv, 3 * Cn, Cn);
    // 4. hyperbolic transform -> split-bf16 q,k,v^T
    transform_kernel<<<(MR * Hn) / 8, 256>>>(qkv, qth, qtl, kth, ktl, vth, vtl);
    // 5. flash attention (tensor cores)
    attn_mma_kernel<<<512, 256, ATTN_SMEM>>>(qth, qtl, kth, ktl, vth, vtl, spk, y);
    // 6. out projection
    conv_rows_kernel<<<(MR * Cn) / 256, 256>>>(y, yh, yl);
    convT_kernel<<<dim3(Cn / 32, Cn / 32), dim3(32, 8)>>>(Wout, woh, wol, Cn, Cn);
    mma_gemm_kernel<<<dim3(Cn / 128, MR / 128), 256, GEMM_SMEM>>>(
        yh, yl, woh, wol, bout, out, Cn, Cn);
}

// round 8
// speedup vs baseline: 3.1902x; 1.0157x over previous
#include <cuda_runtime.h>
#include <cuda_bf16.h>
#include <math.h>
#include <stdint.h>

// Problem constants
#define Bn 4
#define Tn 1024
#define Cn 1024
#define Hn 16
#define Dn 64
#define MR (Bn*Tn)
#define BH (Bn*Hn)

// ---------------- scratch (no allocations allowed) ----------------
__device__ float g_qkv[MR * 3 * Cn];
__device__ float g_spk[MR];
__device__ float g_y  [MR * Cn];
__device__ __nv_bfloat16 g_xh[MR * Cn], g_xl[MR * Cn];
__device__ __nv_bfloat16 g_yh[MR * Cn], g_yl[MR * Cn];
__device__ __nv_bfloat16 g_wqh[3 * Cn * Cn], g_wql[3 * Cn * Cn];
__device__ __nv_bfloat16 g_woh[Cn * Cn], g_wol[Cn * Cn];
// attention operands: [bh][t][d] for q,k; [bh][d][t] for v^T
__device__ __nv_bfloat16 g_qth[BH * Tn * Dn], g_qtl[BH * Tn * Dn];
__device__ __nv_bfloat16 g_kth[BH * Tn * Dn], g_ktl[BH * Tn * Dn];
__device__ __nv_bfloat16 g_vth[BH * Dn * Tn], g_vtl[BH * Dn * Tn];

// ---------------- helpers ----------------
__device__ __forceinline__ uint32_t smem_u32(const void* p) {
    uint32_t a;
    asm("{ .reg .u64 t; cvta.to.shared.u64 t, %1; cvt.u32.u64 %0, t; }" : "=r"(a) : "l"(p));
    return a;
}
__device__ __forceinline__ void cp16(uint32_t dst, const void* src) {
    asm volatile("cp.async.cg.shared.global [%0], [%1], 16;" :: "r"(dst), "l"(src));
}
__device__ __forceinline__ void cp_commit() {
    asm volatile("cp.async.commit_group;" ::: "memory");
}
template <int N>
__device__ __forceinline__ void cp_wait() {
    asm volatile("cp.async.wait_group %0;" :: "n"(N) : "memory");
}
__device__ __forceinline__ void mma16816(float* d, const uint32_t* a, const uint32_t* b) {
    asm volatile(
        "mma.sync.aligned.m16n8k16.row.col.f32.bf16.bf16.f32 "
        "{%0,%1,%2,%3}, {%4,%5,%6,%7}, {%8,%9}, {%0,%1,%2,%3};"
        : "+f"(d[0]), "+f"(d[1]), "+f"(d[2]), "+f"(d[3])
        : "r"(a[0]), "r"(a[1]), "r"(a[2]), "r"(a[3]), "r"(b[0]), "r"(b[1]));
}
__device__ __forceinline__ uint32_t pack_bf16x2(float hi, float lo) {
    uint32_t r;
    asm("cvt.rn.bf16x2.f32 %0, %1, %2;" : "=r"(r) : "f"(hi), "f"(lo));
    return r;
}

// ---------------- fast math (FMA-pipe log/exp) ----------------
__device__ __forceinline__ float fast_log(float a) {   // a >= 1
    int i = __float_as_int(a);
    int e = (i >> 23) - 126;
    float m = __int_as_float((i & 0x007FFFFF) | 0x3F000000);
    if (m < 0.70710678118f) { m = m + m; e -= 1; }
    float x = m - 1.0f;
    float z = x * x;
    float y = 7.0376836292e-2f;
    y = fmaf(y, x, -1.1514610310e-1f);
    y = fmaf(y, x,  1.1676998740e-1f);
    y = fmaf(y, x, -1.2420140846e-1f);
    y = fmaf(y, x,  1.4249322787e-1f);
    y = fmaf(y, x, -1.6668057665e-1f);
    y = fmaf(y, x,  2.0000714765e-1f);
    y = fmaf(y, x, -2.4999993993e-1f);
    y = fmaf(y, x,  3.3333331174e-1f);
    y = y * x * z;
    float ef = (float)e;
    y = fmaf(ef, -2.12194440e-4f, y);
    y = fmaf(-0.5f, z, y);
    float r = x + y;
    return fmaf(ef, 0.693359375f, r);
}
__device__ __forceinline__ float fast_exp_neg(float zin) {  // zin <= 0
    float z = fmaxf(zin, -80.f);
    float fn = fmaf(z, 1.44269504089f, 12582912.f);
    int n = __float_as_int(fn) - 0x4B400000;
    float nf = fn - 12582912.f;
    float r = fmaf(nf, -0.693359375f, z);
    r = fmaf(nf, 2.12194440e-4f, r);
    float y = 1.9875691500e-4f;
    y = fmaf(y, r, 1.3981999507e-3f);
    y = fmaf(y, r, 8.3334519073e-3f);
    y = fmaf(y, r, 4.1665795894e-2f);
    y = fmaf(y, r, 1.6666665459e-1f);
    y = fmaf(y, r, 5.0000001201e-1f);
    float res = fmaf(y * r, r, r) + 1.0f;
    return res * __int_as_float((n + 127) << 23);
}
__device__ __forceinline__ float score_p(float x) {
    float xx = fmaxf(x, 1.0000001f);
    float s2 = fmaf(xx, xx, -1.f);
    float sq;
    asm("sqrt.approx.f32 %0, %1;" : "=f"(sq) : "f"(s2));
    float dist = fast_log(xx + sq);
    return fast_exp_neg(dist * dist * -0.125f);
}

// ---------------- spike / surrogate ----------------
__global__ void spike_kernel(const float* __restrict__ x, const float* __restrict__ w_sur,
                             const float* __restrict__ b_sur, const float* __restrict__ threshold,
                             float* __restrict__ spikes) {
    __shared__ float red[256];
    int bt = blockIdx.x;
    const float* xr = &x[(size_t)bt * Cn];
    float s = 0.f;
    for (int c = threadIdx.x; c < Cn; c += 256) s += xr[c] * w_sur[c];
    red[threadIdx.x] = s;
    __syncthreads();
    for (int o = 128; o; o >>= 1) {
        if (threadIdx.x < o) red[threadIdx.x] += red[threadIdx.x + o];
        __syncthreads();
    }
    if (threadIdx.x == 0) {
        float imp = 1.f / (1.f + expf(-(red[0] + b_sur[0])));
        spikes[bt] = imp > threshold[0] ? 1.f : 0.f;
    }
}

// ---------------- fp32 -> bf16 hi/lo converters ----------------
__global__ void conv_rows_kernel(const float* __restrict__ A,
                                 __nv_bfloat16* __restrict__ h, __nv_bfloat16* __restrict__ l) {
    int i = blockIdx.x * 256 + threadIdx.x;
    float v = A[i];
    __nv_bfloat16 hh = __float2bfloat16(v);
    h[i] = hh;
    l[i] = __float2bfloat16(v - __bfloat162float(hh));
}
__global__ void convT_kernel(const float* __restrict__ W,
                             __nv_bfloat16* __restrict__ th, __nv_bfloat16* __restrict__ tl,
                             int K, int N) {
    __shared__ float t[32][33];
    int n0 = blockIdx.x * 32, k0 = blockIdx.y * 32;
    for (int i = threadIdx.y; i < 32; i += 8)
        t[i][threadIdx.x] = W[(size_t)(k0 + i) * N + n0 + threadIdx.x];
    __syncthreads();
    for (int i = threadIdx.y; i < 32; i += 8) {
        float v = t[threadIdx.x][i];
        __nv_bfloat16 hh = __float2bfloat16(v);
        size_t o = (size_t)(n0 + i) * K + k0 + threadIdx.x;
        th[o] = hh;
        tl[o] = __float2bfloat16(v - __bfloat162float(hh));
    }
}

// ---------------- mma.sync split-bf16 GEMM: 4-stage pipeline, 1 sync/chunk ----------------
#define AH_OFF 0
#define AL_OFF 10240
#define BH_OFF 20480
#define BL_OFF 30720
#define STAGE_B 40960
#define GEMM_SMEM (4 * STAGE_B)

__global__ __launch_bounds__(256) void mma_gemm_kernel(
    const __nv_bfloat16* __restrict__ Ah, const __nv_bfloat16* __restrict__ Al,
    const __nv_bfloat16* __restrict__ Bh, const __nv_bfloat16* __restrict__ Bl,
    const float* __restrict__ bias, float* __restrict__ Cm, int N, int K) {
    extern __shared__ __align__(128) char smem[];
    uint32_t sb = smem_u32(smem);

    int tid = threadIdx.x;
    int lane = tid & 31;
    int w = tid >> 5;
    int wm = w & 3;
    int wn = w >> 2;
    int bm = blockIdx.y * 128;
    int bn = blockIdx.x * 128;

    float acc[2][8][4];
#pragma unroll
    for (int mt = 0; mt < 2; mt++)
#pragma unroll
        for (int nt = 0; nt < 8; nt++)
#pragma unroll
            for (int q = 0; q < 4; q++) acc[mt][nt][q] = 0.f;

    int NK = K / 32;

    auto load_stage = [&](int kc, int s) {
        uint32_t base = sb + s * STAGE_B;
        int k0 = kc * 32;
#pragma unroll
        for (int it = 0; it < 2; it++) {
            int lin = it * 256 + tid;
            int r = lin >> 2, c = lin & 3;
            uint32_t so = (uint32_t)(r * 80 + c * 16);
            size_t go = (size_t)(bm + r) * K + k0 + c * 8;
            cp16(base + AH_OFF + so, Ah + go);
            cp16(base + AL_OFF + so, Al + go);
        }
#pragma unroll
        for (int it = 0; it < 2; it++) {
            int lin = it * 256 + tid;
            int r = lin >> 2, c = lin & 3;
            uint32_t so = (uint32_t)(r * 80 + c * 16);
            size_t go = (size_t)(bn + r) * K + k0 + c * 8;
            cp16(base + BH_OFF + so, Bh + go);
            cp16(base + BL_OFF + so, Bl + go);
        }
        cp_commit();
    };

    // prologue: fill 3 of 4 stages
    load_stage(0, 0);
    load_stage(1, 1);
    load_stage(2, 2);

    int arow = wm * 32 + (lane >> 2);
    int kcol = 2 * (lane & 3);
    int brow = wn * 64 + (lane >> 2);

    for (int kc = 0; kc < NK; kc++) {
        cp_wait<2>();
        __syncthreads();
        // refill the stage all warps provably finished (kc-1)%4 == (kc+3)%4
        if (kc + 3 < NK) load_stage(kc + 3, (kc + 3) & 3);
        else cp_commit();              // keep wait-group accounting invariant

        const char* sm = (const char*)smem + (kc & 3) * STAGE_B;

#pragma unroll
        for (int ks = 0; ks < 2; ks++) {
            int kb = (ks * 16 + kcol) * 2;
            uint32_t ah[2][4], al[2][4];
#pragma unroll
            for (int mt = 0; mt < 2; mt++) {
                int r0 = (arow + mt * 16) * 80 + kb;
                ah[mt][0] = *(const uint32_t*)(sm + AH_OFF + r0);
                ah[mt][1] = *(const uint32_t*)(sm + AH_OFF + r0 + 8 * 80);
                ah[mt][2] = *(const uint32_t*)(sm + AH_OFF + r0 + 16);
                ah[mt][3] = *(const uint32_t*)(sm + AH_OFF + r0 + 8 * 80 + 16);
                al[mt][0] = *(const uint32_t*)(sm + AL_OFF + r0);
                al[mt][1] = *(const uint32_t*)(sm + AL_OFF + r0 + 8 * 80);
                al[mt][2] = *(const uint32_t*)(sm + AL_OFF + r0 + 16);
                al[mt][3] = *(const uint32_t*)(sm + AL_OFF + r0 + 8 * 80 + 16);
            }
#pragma unroll
            for (int nt = 0; nt < 8; nt++) {
                int r0 = (brow + nt * 8) * 80 + kb;
                uint32_t bh[2], bl[2];
                bh[0] = *(const uint32_t*)(sm + BH_OFF + r0);
                bh[1] = *(const uint32_t*)(sm + BH_OFF + r0 + 16);
                bl[0] = *(const uint32_t*)(sm + BL_OFF + r0);
                bl[1] = *(const uint32_t*)(sm + BL_OFF + r0 + 16);
#pragma unroll
                for (int mt = 0; mt < 2; mt++) {
                    mma16816(acc[mt][nt], ah[mt], bh);
                    mma16816(acc[mt][nt], ah[mt], bl);
                    mma16816(acc[mt][nt], al[mt], bh);
                }
            }
        }
        // no trailing sync: next iteration's barrier protects the refill
    }

#pragma unroll
    for (int mt = 0; mt < 2; mt++) {
        int m0 = bm + wm * 32 + mt * 16 + (lane >> 2);
#pragma unroll
        for (int nt = 0; nt < 8; nt++) {
            int c0 = bn + wn * 64 + nt * 8 + 2 * (lane & 3);
            float b0 = bias[c0], b1 = bias[c0 + 1];
            float* p0 = Cm + (size_t)m0 * N + c0;
            p0[0] = acc[mt][nt][0] + b0;
            p0[1] = acc[mt][nt][1] + b1;
            float* p1 = p0 + 8 * (size_t)N;
            p1[0] = acc[mt][nt][2] + b0;
            p1[1] = acc[mt][nt][3] + b1;
        }
    }
}

// ---------------- expmap0 transform: 32 tokens x 1 head per block ----------------
// q/k written directly (coalesced); v staged in smem and written transposed (coalesced).
__global__ __launch_bounds__(256) void transform_kernel(
    const float* __restrict__ qkv,
    __nv_bfloat16* __restrict__ qth, __nv_bfloat16* __restrict__ qtl,
    __nv_bfloat16* __restrict__ kth, __nv_bfloat16* __restrict__ ktl,
    __nv_bfloat16* __restrict__ vth, __nv_bfloat16* __restrict__ vtl) {
    __shared__ float vs[32][67];

    int tb = blockIdx.x;                 // token tile: 32 consecutive bt
    int h = blockIdx.y;
    int w = threadIdx.x >> 5;
    int lane = threadIdx.x & 31;

    int bt0 = tb * 32;
    int b = bt0 / Tn;
    int t0 = bt0 % Tn;
    int bh = b * Hn + h;

#pragma unroll
    for (int it = 0; it < 4; it++) {
        int tl = it * 8 + w;             // local token 0..31
        int bt = bt0 + tl;
        int t = t0 + tl;

        const float* base = &qkv[(size_t)bt * (3 * Cn) + h * Dn];
        float2 uq = ((const float2*)base)[lane];
        float2 uk = ((const float2*)(base + Cn))[lane];
        float2 uv = ((const float2*)(base + 2 * Cn))[lane];

        float sq = uq.y * uq.y + (lane ? uq.x * uq.x : 0.f);
        float sk = uk.y * uk.y + (lane ? uk.x * uk.x : 0.f);
#pragma unroll
        for (int off = 16; off; off >>= 1) {
            sq += __shfl_xor_sync(0xFFFFFFFFu, sq, off);
            sk += __shfl_xor_sync(0xFFFFFFFFu, sk, off);
        }
        float u0q = __shfl_sync(0xFFFFFFFFu, uq.x, 0);
        float u0k = __shfl_sync(0xFFFFFFFFu, uk.x, 0);

        float nq = sqrtf(fmaxf(sq - u0q * u0q, 1e-8f));
        float nk = sqrtf(fmaxf(sk - u0k * u0k, 1e-8f));
        float fq = sinhf(nq) / nq;
        float fk = sinhf(nk) / nk;
        float tmq = coshf(nq);
        float tmk = coshf(nk);

        float2 oq, ok;
        oq.x = lane ? fq * uq.x : tmq;
        oq.y = fq * uq.y;
        ok.x = lane ? -fk * uk.x : tmk;
        ok.y = -fk * uk.y;

        size_t out = ((size_t)bh * Tn + t) * Dn;
        __nv_bfloat16 qx = __float2bfloat16(oq.x), qy = __float2bfloat16(oq.y);
        ((__nv_bfloat162*)(qth + out))[lane] = __nv_bfloat162(qx, qy);
        ((__nv_bfloat162*)(qtl + out))[lane] = __nv_bfloat162(
            __float2bfloat16(oq.x - __bfloat162float(qx)), __float2bfloat16(oq.y - __bfloat162float(qy)));
        __nv_bfloat16 kx = __float2bfloat16(ok.x), ky = __float2bfloat16(ok.y);
        ((__nv_bfloat162*)(kth + out))[lane] = __nv_bfloat162(kx, ky);
        ((__nv_bfloat162*)(ktl + out))[lane] = __nv_bfloat162(
            __float2bfloat16(ok.x - __bfloat162float(kx)), __float2bfloat16(ok.y - __bfloat162float(ky)));

        vs[tl][2 * lane] = uv.x;
        vs[tl][2 * lane + 1] = uv.y;
    }
    __syncthreads();

    // write v^T [bh][d][t0..t0+31], coalesced 64B runs
#pragma unroll
    for (int rep = 0; rep < 8; rep++) {
        int idx = rep * 256 + threadIdx.x;   // 0..2047
        int d = idx >> 5, t = idx & 31;
        float v = vs[t][d];
        __nv_bfloat16 hh = __float2bfloat16(v);
        size_t o = ((size_t)bh * Dn + d) * Tn + t0 + t;
        vth[o] = hh;
        vtl[o] = __float2bfloat16(v - __bfloat162float(hh));
    }
}

// ---------------- flash attention on mma.sync (unchanged from R6) ----------------
#define ATK_OFF 0
#define ATKL_OFF 9216
#define ATV_OFF 18432
#define ATVL_OFF 27648
#define ATSTG 36864
#define ATTN_SMEM (2 * ATSTG)

__global__ __launch_bounds__(256) void attn_mma_kernel(
    const __nv_bfloat16* __restrict__ qth, const __nv_bfloat16* __restrict__ qtl,
    const __nv_bfloat16* __restrict__ kth, const __nv_bfloat16* __restrict__ ktl,
    const __nv_bfloat16* __restrict__ vth, const __nv_bfloat16* __restrict__ vtl,
    const float* __restrict__ spikes, float* __restrict__ y) {
    extern __shared__ __align__(128) char smem[];
    uint32_t sb = smem_u32(smem);

    int tid = threadIdx.x;
    int lane = tid & 31;
    int w = tid >> 5;

    int idx = blockIdx.x;
    int qt = 7 - (idx >> 6);
    int bh = idx & 63;
    int b = bh >> 4, h = bh & 15;
    int q0 = qt * 128;

    size_t qoff = ((size_t)bh * Tn + q0) * Dn;
#pragma unroll
    for (int it = 0; it < 4; it++) {
        int lin = it * 256 + tid;
        int r = lin >> 3, c = lin & 7;
        cp16(sb + (uint32_t)(r * 144 + c * 16), qth + qoff + r * 64 + c * 8);
        cp16(sb + 18432u + (uint32_t)(r * 144 + c * 16), qtl + qoff + r * 64 + c * 8);
    }
    cp_commit();

    size_t kbase = (size_t)bh * Tn * Dn;
    size_t vbase = (size_t)bh * Dn * Tn;
    auto load_tile = [&](int t, int s) {
        uint32_t base = sb + s * ATSTG;
        int k0 = t * 64;
#pragma unroll
        for (int it = 0; it < 2; it++) {
            int lin = it * 256 + tid;
            int r = lin >> 3, c = lin & 7;
            uint32_t so = (uint32_t)(r * 144 + c * 16);
            cp16(base + ATK_OFF + so, kth + kbase + (size_t)(k0 + r) * 64 + c * 8);
            cp16(base + ATKL_OFF + so, ktl + kbase + (size_t)(k0 + r) * 64 + c * 8);
            cp16(base + ATV_OFF + so, vth + vbase + (size_t)r * Tn + k0 + c * 8);
            cp16(base + ATVL_OFF + so, vtl + vbase + (size_t)r * Tn + k0 + c * 8);
        }
        cp_commit();
    };

    load_tile(0, 1);

    cp_wait<1>();
    __syncthreads();

    int rowi = lane >> 2;
    int qrow = w * 16 + rowi;
    uint32_t qfh[4][4], qfl[4][4];
#pragma unroll
    for (int ks = 0; ks < 4; ks++) {
        int cb = (ks * 16 + 2 * (lane & 3)) * 2;
        const char* qs = smem;
        const char* qsl = smem + 18432;
        qfh[ks][0] = *(const uint32_t*)(qs + qrow * 144 + cb);
        qfh[ks][1] = *(const uint32_t*)(qs + (qrow + 8) * 144 + cb);
        qfh[ks][2] = *(const uint32_t*)(qs + qrow * 144 + cb + 16);
        qfh[ks][3] = *(const uint32_t*)(qs + (qrow + 8) * 144 + cb + 16);
        qfl[ks][0] = *(const uint32_t*)(qsl + qrow * 144 + cb);
        qfl[ks][1] = *(const uint32_t*)(qsl + (qrow + 8) * 144 + cb);
        qfl[ks][2] = *(const uint32_t*)(qsl + qrow * 144 + cb + 16);
        qfl[ks][3] = *(const uint32_t*)(qsl + (qrow + 8) * 144 + cb + 16);
    }
    __syncthreads();

    float O[8][4];
#pragma unroll
    for (int nt = 0; nt < 8; nt++)
#pragma unroll
        for (int q = 0; q < 4; q++) O[nt][q] = 0.f;
    float l0 = 0.f, l1 = 0.f;

    int r0g = q0 + w * 16 + rowi;
    int r1g = r0g + 8;

    int ntiles = qt * 2 + 2;
    for (int t = 0; t < ntiles; t++) {
        if (t + 1 < ntiles) { load_tile(t + 1, t & 1); cp_wait<1>(); }
        else cp_wait<0>();
        __syncthreads();

        int s = (t + 1) & 1;
        const char* Khs = smem + s * ATSTG + ATK_OFF;
        const char* Kls = smem + s * ATSTG + ATKL_OFF;
        const char* Vhs = smem + s * ATSTG + ATV_OFF;
        const char* Vls = smem + s * ATSTG + ATVL_OFF;
        int k0 = t * 64;

        float S[8][4];
#pragma unroll
        for (int nt = 0; nt < 8; nt++)
#pragma unroll
            for (int q = 0; q < 4; q++) S[nt][q] = 0.f;
#pragma unroll
        for (int ks = 0; ks < 4; ks++) {
            int cb = (ks * 16 + 2 * (lane & 3)) * 2;
#pragma unroll
            for (int nt = 0; nt < 8; nt++) {
                int keyr = nt * 8 + rowi;
                uint32_t bhf[2], blf[2];
                bhf[0] = *(const uint32_t*)(Khs + keyr * 144 + cb);
                bhf[1] = *(const uint32_t*)(Khs + keyr * 144 + cb + 16);
                blf[0] = *(const uint32_t*)(Kls + keyr * 144 + cb);
                blf[1] = *(const uint32_t*)(Kls + keyr * 144 + cb + 16);
                mma16816(S[nt], qfh[ks], bhf);
                mma16816(S[nt], qfh[ks], blf);
                mma16816(S[nt], qfl[ks], bhf);
            }
        }

        uint32_t pha[4][4], pla[4][4];
#pragma unroll
        for (int nt = 0; nt < 8; nt++) {
            int jj0 = k0 + nt * 8 + 2 * (lane & 3);
            float p0 = score_p(S[nt][0]);
            float p1 = score_p(S[nt][1]);
            float p2 = score_p(S[nt][2]);
            float p3 = score_p(S[nt][3]);
            p0 = (jj0 <= r0g) ? p0 : 0.f;
            p1 = (jj0 + 1 <= r0g) ? p1 : 0.f;
            p2 = (jj0 <= r1g) ? p2 : 0.f;
            p3 = (jj0 + 1 <= r1g) ? p3 : 0.f;
            l0 += p0 + p1;
            l1 += p2 + p3;
            uint32_t h01 = pack_bf16x2(p1, p0);
            uint32_t h23 = pack_bf16x2(p3, p2);
            float f0 = __int_as_float(h01 << 16);
            float f1 = __int_as_float(h01 & 0xFFFF0000u);
            float f2 = __int_as_float(h23 << 16);
            float f3 = __int_as_float(h23 & 0xFFFF0000u);
            uint32_t l01 = pack_bf16x2(p1 - f1, p0 - f0);
            uint32_t l23 = pack_bf16x2(p3 - f3, p2 - f2);
            int js = nt >> 1, hf = nt & 1;
            pha[js][0 + 2 * hf] = h01;
            pha[js][1 + 2 * hf] = h23;
            pla[js][0 + 2 * hf] = l01;
            pla[js][1 + 2 * hf] = l23;
        }

#pragma unroll
        for (int js = 0; js < 4; js++) {
            int kb = (js * 16 + 2 * (lane & 3)) * 2;
#pragma unroll
            for (int nt = 0; nt < 8; nt++) {
                int dimr = nt * 8 + rowi;
                uint32_t vhf[2], vlf[2];
                vhf[0] = *(const uint32_t*)(Vhs + dimr * 144 + kb);
                vhf[1] = *(const uint32_t*)(Vhs + dimr * 144 + kb + 16);
                vlf[0] = *(const uint32_t*)(Vls + dimr * 144 + kb);
                vlf[1] = *(const uint32_t*)(Vls + dimr * 144 + kb + 16);
                mma16816(O[nt], pha[js], vhf);
                mma16816(O[nt], pha[js], vlf);
                mma16816(O[nt], pla[js], vhf);
            }
        }
        __syncthreads();
    }

    l0 += __shfl_xor_sync(0xFFFFFFFFu, l0, 1);
    l0 += __shfl_xor_sync(0xFFFFFFFFu, l0, 2);
    l1 += __shfl_xor_sync(0xFFFFFFFFu, l1, 1);
    l1 += __shfl_xor_sync(0xFFFFFFFFu, l1, 2);

    float inv0 = spikes[b * Tn + r0g] / l0;
    float inv1 = spikes[b * Tn + r1g] / l1;

#pragma unroll
    for (int nt = 0; nt < 8; nt++) {
        int col = h * 64 + nt * 8 + 2 * (lane & 3);
        float2 o0 = make_float2(O[nt][0] * inv0, O[nt][1] * inv0);
        float2 o1 = make_float2(O[nt][2] * inv1, O[nt][3] * inv1);
        *(float2*)&y[((size_t)(b * Tn + r0g)) * Cn + col] = o0;
        *(float2*)&y[((size_t)(b * Tn + r1g)) * Cn + col] = o1;
    }
}

// ---------------- launcher ----------------
extern "C" void kernel_launch(void* const* d_in, const int* in_sizes, int n_in,
                              void* d_out, int out_size) {
    const float* x    = (const float*)d_in[0];
    const float* Wqkv = (const float*)d_in[1];
    const float* bqkv = (const float*)d_in[2];
    const float* Wout = (const float*)d_in[3];
    const float* bout = (const float*)d_in[4];
    const float* wsur = (const float*)d_in[5];
    const float* bsur = (const float*)d_in[6];
    const float* thr  = (const float*)d_in[7];
    float* out = (float*)d_out;

    float *qkv, *spk, *y;
    __nv_bfloat16 *xh, *xl, *yh, *yl, *wqh, *wql, *woh, *wol;
    __nv_bfloat16 *qth, *qtl, *kth, *ktl, *vth, *vtl;
    cudaGetSymbolAddress((void**)&qkv, g_qkv);
    cudaGetSymbolAddress((void**)&spk, g_spk);
    cudaGetSymbolAddress((void**)&y, g_y);
    cudaGetSymbolAddress((void**)&xh, g_xh);
    cudaGetSymbolAddress((void**)&xl, g_xl);
    cudaGetSymbolAddress((void**)&yh, g_yh);
    cudaGetSymbolAddress((void**)&yl, g_yl);
    cudaGetSymbolAddress((void**)&wqh, g_wqh);
    cudaGetSymbolAddress((void**)&wql, g_wql);
    cudaGetSymbolAddress((void**)&woh, g_woh);
    cudaGetSymbolAddress((void**)&wol, g_wol);
    cudaGetSymbolAddress((void**)&qth, g_qth);
    cudaGetSymbolAddress((void**)&qtl, g_qtl);
    cudaGetSymbolAddress((void**)&kth, g_kth);
    cudaGetSymbolAddress((void**)&ktl, g_ktl);
    cudaGetSymbolAddress((void**)&vth, g_vth);
    cudaGetSymbolAddress((void**)&vtl, g_vtl);

    cudaFuncSetAttribute(mma_gemm_kernel, cudaFuncAttributeMaxDynamicSharedMemorySize, GEMM_SMEM);
    cudaFuncSetAttribute(attn_mma_kernel, cudaFuncAttributeMaxDynamicSharedMemorySize, ATTN_SMEM);

    // 1. spikes
    spike_kernel<<<MR, 256>>>(x, wsur, bsur, thr, spk);
    // 2. split-bf16 conversions
    conv_rows_kernel<<<(MR * Cn) / 256, 256>>>(x, xh, xl);
    convT_kernel<<<dim3(3 * Cn / 32, Cn / 32), dim3(32, 8)>>>(Wqkv, wqh, wql, Cn, 3 * Cn);
    // 3. qkv = x @ W_qkv + b
    mma_gemm_kernel<<<dim3(3 * Cn / 128, MR / 128), 256, GEMM_SMEM>>>(
        xh, xl, wqh, wql, bqkv, qkv, 3 * Cn, Cn);
    // 4. hyperbolic transform -> split-bf16 q,k,v^T
    transform_kernel<<<dim3(MR / 32, Hn), 256>>>(qkv, qth, qtl, kth, ktl, vth, vtl);
    // 5. flash attention (tensor cores)
    attn_mma_kernel<<<512, 256, ATTN_SMEM>>>(qth, qtl, kth, ktl, vth, vtl, spk, y);
    // 6. out projection
    conv_rows_kernel<<<(MR * Cn) / 256, 256>>>(y, yh, yl);
    convT_kernel<<<dim3(Cn / 32, Cn / 32), dim3(32, 8)>>>(Wout, woh, wol, Cn, Cn);
    mma_gemm_kernel<<<dim3(Cn / 128, MR / 128), 256, GEMM_SMEM>>>(
        yh, yl, woh, wol, bout, out, Cn, Cn);
}

// round 10
// speedup vs baseline: 3.2337x; 1.0136x over previous
#include <cuda_runtime.h>
#include <cuda_bf16.h>
#include <math.h>
#include <stdint.h>

// Problem constants
#define Bn 4
#define Tn 1024
#define Cn 1024
#define Hn 16
#define Dn 64
#define MR (Bn*Tn)
#define BH (Bn*Hn)

// ---------------- scratch (no allocations allowed) ----------------
__device__ float g_qkv[MR * 3 * Cn];
__device__ float g_spk[MR];
__device__ float g_y  [MR * Cn];
__device__ __nv_bfloat16 g_xh[MR * Cn], g_xl[MR * Cn];
__device__ __nv_bfloat16 g_yh[MR * Cn], g_yl[MR * Cn];
__device__ __nv_bfloat16 g_wqh[3 * Cn * Cn], g_wql[3 * Cn * Cn];
__device__ __nv_bfloat16 g_woh[Cn * Cn], g_wol[Cn * Cn];
__device__ __nv_bfloat16 g_qth[BH * Tn * Dn], g_qtl[BH * Tn * Dn];
__device__ __nv_bfloat16 g_kth[BH * Tn * Dn], g_ktl[BH * Tn * Dn];
__device__ __nv_bfloat16 g_vth[BH * Dn * Tn], g_vtl[BH * Dn * Tn];

// ---------------- helpers ----------------
__device__ __forceinline__ uint32_t smem_u32(const void* p) {
    uint32_t a;
    asm("{ .reg .u64 t; cvta.to.shared.u64 t, %1; cvt.u32.u64 %0, t; }" : "=r"(a) : "l"(p));
    return a;
}
__device__ __forceinline__ void cp16(uint32_t dst, const void* src) {
    asm volatile("cp.async.cg.shared.global [%0], [%1], 16;" :: "r"(dst), "l"(src));
}
__device__ __forceinline__ void cp_commit() {
    asm volatile("cp.async.commit_group;" ::: "memory");
}
template <int N>
__device__ __forceinline__ void cp_wait() {
    asm volatile("cp.async.wait_group %0;" :: "n"(N) : "memory");
}
__device__ __forceinline__ void mma16816(float* d, const uint32_t* a, const uint32_t* b) {
    asm volatile(
        "mma.sync.aligned.m16n8k16.row.col.f32.bf16.bf16.f32 "
        "{%0,%1,%2,%3}, {%4,%5,%6,%7}, {%8,%9}, {%0,%1,%2,%3};"
        : "+f"(d[0]), "+f"(d[1]), "+f"(d[2]), "+f"(d[3])
        : "r"(a[0]), "r"(a[1]), "r"(a[2]), "r"(a[3]), "r"(b[0]), "r"(b[1]));
}
__device__ __forceinline__ void ldsm4(uint32_t* r, uint32_t addr) {
    asm volatile("ldmatrix.sync.aligned.m8n8.x4.shared.b16 {%0,%1,%2,%3}, [%4];"
        : "=r"(r[0]), "=r"(r[1]), "=r"(r[2]), "=r"(r[3]) : "r"(addr));
}
__device__ __forceinline__ uint32_t pack_bf16x2(float hi, float lo) {
    uint32_t r;
    asm("cvt.rn.bf16x2.f32 %0, %1, %2;" : "=r"(r) : "f"(hi), "f"(lo));
    return r;
}

// ---------------- fast math (FMA-pipe log/exp) ----------------
__device__ __forceinline__ float fast_log(float a) {   // a >= 1
    int i = __float_as_int(a);
    int e = (i >> 23) - 126;
    float m = __int_as_float((i & 0x007FFFFF) | 0x3F000000);
    if (m < 0.70710678118f) { m = m + m; e -= 1; }
    float x = m - 1.0f;
    float z = x * x;
    float y = 7.0376836292e-2f;
    y = fmaf(y, x, -1.1514610310e-1f);
    y = fmaf(y, x,  1.1676998740e-1f);
    y = fmaf(y, x, -1.2420140846e-1f);
    y = fmaf(y, x,  1.4249322787e-1f);
    y = fmaf(y, x, -1.6668057665e-1f);
    y = fmaf(y, x,  2.0000714765e-1f);
    y = fmaf(y, x, -2.4999993993e-1f);
    y = fmaf(y, x,  3.3333331174e-1f);
    y = y * x * z;
    float ef = (float)e;
    y = fmaf(ef, -2.12194440e-4f, y);
    y = fmaf(-0.5f, z, y);
    float r = x + y;
    return fmaf(ef, 0.693359375f, r);
}
__device__ __forceinline__ float fast_exp_neg(float zin) {  // zin <= 0
    float z = fmaxf(zin, -80.f);
    float fn = fmaf(z, 1.44269504089f, 12582912.f);
    int n = __float_as_int(fn) - 0x4B400000;
    float nf = fn - 12582912.f;
    float r = fmaf(nf, -0.693359375f, z);
    r = fmaf(nf, 2.12194440e-4f, r);
    float y = 1.9875691500e-4f;
    y = fmaf(y, r, 1.3981999507e-3f);
    y = fmaf(y, r, 8.3334519073e-3f);
    y = fmaf(y, r, 4.1665795894e-2f);
    y = fmaf(y, r, 1.6666665459e-1f);
    y = fmaf(y, r, 5.0000001201e-1f);
    float res = fmaf(y * r, r, r) + 1.0f;
    return res * __int_as_float((n + 127) << 23);
}
__device__ __forceinline__ float score_p(float x) {
    float xx = fmaxf(x, 1.0000001f);
    float s2 = fmaf(xx, xx, -1.f);
    float sq;
    asm("sqrt.approx.f32 %0, %1;" : "=f"(sq) : "f"(s2));
    float dist = fast_log(xx + sq);
    return fast_exp_neg(dist * dist * -0.125f);
}

// ---------------- spike / surrogate ----------------
__global__ void spike_kernel(const float* __restrict__ x, const float* __restrict__ w_sur,
                             const float* __restrict__ b_sur, const float* __restrict__ threshold,
                             float* __restrict__ spikes) {
    __shared__ float red[256];
    int bt = blockIdx.x;
    const float* xr = &x[(size_t)bt * Cn];
    float s = 0.f;
    for (int c = threadIdx.x; c < Cn; c += 256) s += xr[c] * w_sur[c];
    red[threadIdx.x] = s;
    __syncthreads();
    for (int o = 128; o; o >>= 1) {
        if (threadIdx.x < o) red[threadIdx.x] += red[threadIdx.x + o];
        __syncthreads();
    }
    if (threadIdx.x == 0) {
        float imp = 1.f / (1.f + expf(-(red[0] + b_sur[0])));
        spikes[bt] = imp > threshold[0] ? 1.f : 0.f;
    }
}

// ---------------- fp32 -> bf16 hi/lo converters ----------------
__global__ void conv_rows_kernel(const float* __restrict__ A,
                                 __nv_bfloat16* __restrict__ h, __nv_bfloat16* __restrict__ l) {
    int i = blockIdx.x * 256 + threadIdx.x;
    float v = A[i];
    __nv_bfloat16 hh = __float2bfloat16(v);
    h[i] = hh;
    l[i] = __float2bfloat16(v - __bfloat162float(hh));
}
__global__ void convT_kernel(const float* __restrict__ W,
                             __nv_bfloat16* __restrict__ th, __nv_bfloat16* __restrict__ tl,
                             int K, int N) {
    __shared__ float t[32][33];
    int n0 = blockIdx.x * 32, k0 = blockIdx.y * 32;
    for (int i = threadIdx.y; i < 32; i += 8)
        t[i][threadIdx.x] = W[(size_t)(k0 + i) * N + n0 + threadIdx.x];
    __syncthreads();
    for (int i = threadIdx.y; i < 32; i += 8) {
        float v = t[threadIdx.x][i];
        __nv_bfloat16 hh = __float2bfloat16(v);
        size_t o = (size_t)(n0 + i) * K + k0 + threadIdx.x;
        th[o] = hh;
        tl[o] = __float2bfloat16(v - __bfloat162float(hh));
    }
}

// ---------------- mma.sync split-bf16 GEMM: 2-stage + ldmatrix ----------------
#define AH_OFF 0
#define AL_OFF 10240
#define BH_OFF 20480
#define BL_OFF 30720
#define STAGE_B 40960
#define GEMM_SMEM (2 * STAGE_B)

__global__ __launch_bounds__(256) void mma_gemm_kernel(
    const __nv_bfloat16* __restrict__ Ah, const __nv_bfloat16* __restrict__ Al,
    const __nv_bfloat16* __restrict__ Bh, const __nv_bfloat16* __restrict__ Bl,
    const float* __restrict__ bias, float* __restrict__ Cm, int N, int K) {
    extern __shared__ __align__(128) char smem[];
    uint32_t sb = smem_u32(smem);

    int tid = threadIdx.x;
    int lane = tid & 31;
    int w = tid >> 5;
    int wm = w & 3;
    int wn = w >> 2;
    int bm = blockIdx.y * 128;
    int bn = blockIdx.x * 128;

    float acc[2][8][4];
#pragma unroll
    for (int mt = 0; mt < 2; mt++)
#pragma unroll
        for (int nt = 0; nt < 8; nt++)
#pragma unroll
            for (int q = 0; q < 4; q++) acc[mt][nt][q] = 0.f;

    int NK = K / 32;

    auto load_stage = [&](int kc, int s) {
        uint32_t base = sb + s * STAGE_B;
        int k0 = kc * 32;
        // hi planes first: if a stage is late, hi arrives earliest
#pragma unroll
        for (int it = 0; it < 2; it++) {
            int lin = it * 256 + tid;
            int r = lin >> 2, c = lin & 3;
            uint32_t so = (uint32_t)(r * 80 + c * 16);
            cp16(base + AH_OFF + so, Ah + (size_t)(bm + r) * K + k0 + c * 8);
            cp16(base + BH_OFF + so, Bh + (size_t)(bn + r) * K + k0 + c * 8);
        }
#pragma unroll
        for (int it = 0; it < 2; it++) {
            int lin = it * 256 + tid;
            int r = lin >> 2, c = lin & 3;
            uint32_t so = (uint32_t)(r * 80 + c * 16);
            cp16(base + AL_OFF + so, Al + (size_t)(bm + r) * K + k0 + c * 8);
            cp16(base + BL_OFF + so, Bl + (size_t)(bn + r) * K + k0 + c * 8);
        }
        cp_commit();
    };

    load_stage(0, 0);

    // ldmatrix lane addressing: lanes 0-15 -> rows 0-15 @ +0B, lanes 16-31 -> rows 0-15 @ +16B
    uint32_t l15 = lane & 15;
    uint32_t lhi = (lane >> 4) * 16;

    for (int kc = 0; kc < NK; kc++) {
        if (kc + 1 < NK) { load_stage(kc + 1, (kc + 1) & 1); cp_wait<1>(); }
        else cp_wait<0>();
        __syncthreads();

        uint32_t base = sb + (kc & 1) * STAGE_B;

#pragma unroll
        for (int ks = 0; ks < 2; ks++) {
            uint32_t ah[2][4], al[2][4];
#pragma unroll
            for (int mt = 0; mt < 2; mt++) {
                uint32_t off = (uint32_t)((wm * 32 + mt * 16 + l15) * 80) + ks * 32 + lhi;
                ldsm4(ah[mt], base + AH_OFF + off);
                ldsm4(al[mt], base + AL_OFF + off);
            }
#pragma unroll
            for (int ntp = 0; ntp < 4; ntp++) {
                uint32_t off = (uint32_t)((wn * 64 + ntp * 16 + l15) * 80) + ks * 32 + lhi;
                uint32_t bhp[4], blp[4];
                ldsm4(bhp, base + BH_OFF + off);
                ldsm4(blp, base + BL_OFF + off);
#pragma unroll
                for (int sub = 0; sub < 2; sub++) {
                    int nt = ntp * 2 + sub;
                    uint32_t bh2[2] = { bhp[sub], bhp[2 + sub] };
                    uint32_t bl2[2] = { blp[sub], blp[2 + sub] };
#pragma unroll
                    for (int mt = 0; mt < 2; mt++) {
                        mma16816(acc[mt][nt], ah[mt], bh2);
                        mma16816(acc[mt][nt], ah[mt], bl2);
                        mma16816(acc[mt][nt], al[mt], bh2);
                    }
                }
            }
        }
        __syncthreads();
    }

#pragma unroll
    for (int mt = 0; mt < 2; mt++) {
        int m0 = bm + wm * 32 + mt * 16 + (lane >> 2);
#pragma unroll
        for (int nt = 0; nt < 8; nt++) {
            int c0 = bn + wn * 64 + nt * 8 + 2 * (lane & 3);
            float b0 = bias[c0], b1 = bias[c0 + 1];
            float* p0 = Cm + (size_t)m0 * N + c0;
            p0[0] = acc[mt][nt][0] + b0;
            p0[1] = acc[mt][nt][1] + b1;
            float* p1 = p0 + 8 * (size_t)N;
            p1[0] = acc[mt][nt][2] + b0;
            p1[1] = acc[mt][nt][3] + b1;
        }
    }
}

// ---------------- expmap0 transform: 32 tokens x 1 head per block ----------------
__global__ __launch_bounds__(256) void transform_kernel(
    const float* __restrict__ qkv,
    __nv_bfloat16* __restrict__ qth, __nv_bfloat16* __restrict__ qtl,
    __nv_bfloat16* __restrict__ kth, __nv_bfloat16* __restrict__ ktl,
    __nv_bfloat16* __restrict__ vth, __nv_bfloat16* __restrict__ vtl) {
    __shared__ float vs[32][67];

    int tb = blockIdx.x;
    int h = blockIdx.y;
    int w = threadIdx.x >> 5;
    int lane = threadIdx.x & 31;

    int bt0 = tb * 32;
    int b = bt0 / Tn;
    int t0 = bt0 % Tn;
    int bh = b * Hn + h;

#pragma unroll
    for (int it = 0; it < 4; it++) {
        int tl = it * 8 + w;
        int bt = bt0 + tl;
        int t = t0 + tl;

        const float* base = &qkv[(size_t)bt * (3 * Cn) + h * Dn];
        float2 uq = ((const float2*)base)[lane];
        float2 uk = ((const float2*)(base + Cn))[lane];
        float2 uv = ((const float2*)(base + 2 * Cn))[lane];

        float sq = uq.y * uq.y + (lane ? uq.x * uq.x : 0.f);
        float sk = uk.y * uk.y + (lane ? uk.x * uk.x : 0.f);
#pragma unroll
        for (int off = 16; off; off >>= 1) {
            sq += __shfl_xor_sync(0xFFFFFFFFu, sq, off);
            sk += __shfl_xor_sync(0xFFFFFFFFu, sk, off);
        }
        float u0q = __shfl_sync(0xFFFFFFFFu, uq.x, 0);
        float u0k = __shfl_sync(0xFFFFFFFFu, uk.x, 0);

        float nq = sqrtf(fmaxf(sq - u0q * u0q, 1e-8f));
        float nk = sqrtf(fmaxf(sk - u0k * u0k, 1e-8f));
        float fq = sinhf(nq) / nq;
        float fk = sinhf(nk) / nk;
        float tmq = coshf(nq);
        float tmk = coshf(nk);

        float2 oq, ok;
        oq.x = lane ? fq * uq.x : tmq;
        oq.y = fq * uq.y;
        ok.x = lane ? -fk * uk.x : tmk;
        ok.y = -fk * uk.y;

        size_t out = ((size_t)bh * Tn + t) * Dn;
        __nv_bfloat16 qx = __float2bfloat16(oq.x), qy = __float2bfloat16(oq.y);
        ((__nv_bfloat162*)(qth + out))[lane] = __nv_bfloat162(qx, qy);
        ((__nv_bfloat162*)(qtl + out))[lane] = __nv_bfloat162(
            __float2bfloat16(oq.x - __bfloat162float(qx)), __float2bfloat16(oq.y - __bfloat162float(qy)));
        __nv_bfloat16 kx = __float2bfloat16(ok.x), ky = __float2bfloat16(ok.y);
        ((__nv_bfloat162*)(kth + out))[lane] = __nv_bfloat162(kx, ky);
        ((__nv_bfloat162*)(ktl + out))[lane] = __nv_bfloat162(
            __float2bfloat16(ok.x - __bfloat162float(kx)), __float2bfloat16(ok.y - __bfloat162float(ky)));

        vs[tl][2 * lane] = uv.x;
        vs[tl][2 * lane + 1] = uv.y;
    }
    __syncthreads();

#pragma unroll
    for (int rep = 0; rep < 8; rep++) {
        int idx = rep * 256 + threadIdx.x;
        int d = idx >> 5, t = idx & 31;
        float v = vs[t][d];
        __nv_bfloat16 hh = __float2bfloat16(v);
        size_t o = ((size_t)bh * Dn + d) * Tn + t0 + t;
        vth[o] = hh;
        vtl[o] = __float2bfloat16(v - __bfloat162float(hh));
    }
}

// ---------------- flash attention on mma.sync + ldmatrix ----------------
#define ATK_OFF 0
#define ATKL_OFF 9216
#define ATV_OFF 18432
#define ATVL_OFF 27648
#define ATSTG 36864
#define ATTN_SMEM (2 * ATSTG)

__global__ __launch_bounds__(256) void attn_mma_kernel(
    const __nv_bfloat16* __restrict__ qth, const __nv_bfloat16* __restrict__ qtl,
    const __nv_bfloat16* __restrict__ kth, const __nv_bfloat16* __restrict__ ktl,
    const __nv_bfloat16* __restrict__ vth, const __nv_bfloat16* __restrict__ vtl,
    const float* __restrict__ spikes, float* __restrict__ y) {
    extern __shared__ __align__(128) char smem[];
    uint32_t sb = smem_u32(smem);

    int tid = threadIdx.x;
    int lane = tid & 31;
    int w = tid >> 5;

    int idx = blockIdx.x;
    int qt = 7 - (idx >> 6);
    int bh = idx & 63;
    int b = bh >> 4, h = bh & 15;
    int q0 = qt * 128;

    size_t qoff = ((size_t)bh * Tn + q0) * Dn;
#pragma unroll
    for (int it = 0; it < 4; it++) {
        int lin = it * 256 + tid;
        int r = lin >> 3, c = lin & 7;
        cp16(sb + (uint32_t)(r * 144 + c * 16), qth + qoff + r * 64 + c * 8);
        cp16(sb + 18432u + (uint32_t)(r * 144 + c * 16), qtl + qoff + r * 64 + c * 8);
    }
    cp_commit();

    size_t kbase = (size_t)bh * Tn * Dn;
    size_t vbase = (size_t)bh * Dn * Tn;
    auto load_tile = [&](int t, int s) {
        uint32_t base = sb + s * ATSTG;
        int k0 = t * 64;
#pragma unroll
        for (int it = 0; it < 2; it++) {
            int lin = it * 256 + tid;
            int r = lin >> 3, c = lin & 7;
            uint32_t so = (uint32_t)(r * 144 + c * 16);
            cp16(base + ATK_OFF + so, kth + kbase + (size_t)(k0 + r) * 64 + c * 8);
            cp16(base + ATKL_OFF + so, ktl + kbase + (size_t)(k0 + r) * 64 + c * 8);
            cp16(base + ATV_OFF + so, vth + vbase + (size_t)r * Tn + k0 + c * 8);
            cp16(base + ATVL_OFF + so, vtl + vbase + (size_t)r * Tn + k0 + c * 8);
        }
        cp_commit();
    };

    load_tile(0, 1);

    cp_wait<1>();
    __syncthreads();

    int rowi = lane >> 2;
    int qrow = w * 16 + rowi;
    uint32_t qfh[4][4], qfl[4][4];
#pragma unroll
    for (int ks = 0; ks < 4; ks++) {
        int cb = (ks * 16 + 2 * (lane & 3)) * 2;
        const char* qs = smem;
        const char* qsl = smem + 18432;
        qfh[ks][0] = *(const uint32_t*)(qs + qrow * 144 + cb);
        qfh[ks][1] = *(const uint32_t*)(qs + (qrow + 8) * 144 + cb);
        qfh[ks][2] = *(const uint32_t*)(qs + qrow * 144 + cb + 16);
        qfh[ks][3] = *(const uint32_t*)(qs + (qrow + 8) * 144 + cb + 16);
        qfl[ks][0] = *(const uint32_t*)(qsl + qrow * 144 + cb);
        qfl[ks][1] = *(const uint32_t*)(qsl + (qrow + 8) * 144 + cb);
        qfl[ks][2] = *(const uint32_t*)(qsl + qrow * 144 + cb + 16);
        qfl[ks][3] = *(const uint32_t*)(qsl + (qrow + 8) * 144 + cb + 16);
    }
    __syncthreads();

    float O[8][4];
#pragma unroll
    for (int nt = 0; nt < 8; nt++)
#pragma unroll
        for (int q = 0; q < 4; q++) O[nt][q] = 0.f;
    float l0 = 0.f, l1 = 0.f;

    int r0g = q0 + w * 16 + rowi;
    int r1g = r0g + 8;

    uint32_t l15 = lane & 15;
    uint32_t lhi = (lane >> 4) * 16;

    int ntiles = qt * 2 + 2;
    for (int t = 0; t < ntiles; t++) {
        if (t + 1 < ntiles) { load_tile(t + 1, t & 1); cp_wait<1>(); }
        else cp_wait<0>();
        __syncthreads();

        int s = (t + 1) & 1;
        uint32_t stg = sb + s * ATSTG;
        int k0 = t * 64;

        // ---- S = Q K^T (3-pass split) with ldmatrix K fragments ----
        float S[8][4];
#pragma unroll
        for (int nt = 0; nt < 8; nt++)
#pragma unroll
            for (int q = 0; q < 4; q++) S[nt][q] = 0.f;
#pragma unroll
        for (int ks = 0; ks < 4; ks++) {
#pragma unroll
            for (int ntp = 0; ntp < 4; ntp++) {
                uint32_t off = (ntp * 16 + l15) * 144 + ks * 32 + lhi;
                uint32_t bhp[4], blp[4];
                ldsm4(bhp, stg + ATK_OFF + off);
                ldsm4(blp, stg + ATKL_OFF + off);
#pragma unroll
                for (int sub = 0; sub < 2; sub++) {
                    int nt = ntp * 2 + sub;
                    uint32_t bh2[2] = { bhp[sub], bhp[2 + sub] };
                    uint32_t bl2[2] = { blp[sub], blp[2 + sub] };
                    mma16816(S[nt], qfh[ks], bh2);
                    mma16816(S[nt], qfh[ks], bl2);
                    mma16816(S[nt], qfl[ks], bh2);
                }
            }
        }

        // ---- transform scores -> p, pack to A-fragments ----
        uint32_t pha[4][4], pla[4][4];
#pragma unroll
        for (int nt = 0; nt < 8; nt++) {
            int jj0 = k0 + nt * 8 + 2 * (lane & 3);
            float p0 = score_p(S[nt][0]);
            float p1 = score_p(S[nt][1]);
            float p2 = score_p(S[nt][2]);
            float p3 = score_p(S[nt][3]);
            p0 = (jj0 <= r0g) ? p0 : 0.f;
            p1 = (jj0 + 1 <= r0g) ? p1 : 0.f;
            p2 = (jj0 <= r1g) ? p2 : 0.f;
            p3 = (jj0 + 1 <= r1g) ? p3 : 0.f;
            l0 += p0 + p1;
            l1 += p2 + p3;
            uint32_t h01 = pack_bf16x2(p1, p0);
            uint32_t h23 = pack_bf16x2(p3, p2);
            float f0 = __int_as_float(h01 << 16);
            float f1 = __int_as_float(h01 & 0xFFFF0000u);
            float f2 = __int_as_float(h23 << 16);
            float f3 = __int_as_float(h23 & 0xFFFF0000u);
            uint32_t l01 = pack_bf16x2(p1 - f1, p0 - f0);
            uint32_t l23 = pack_bf16x2(p3 - f3, p2 - f2);
            int js = nt >> 1, hf = nt & 1;
            pha[js][0 + 2 * hf] = h01;
            pha[js][1 + 2 * hf] = h23;
            pla[js][0 + 2 * hf] = l01;
            pla[js][1 + 2 * hf] = l23;
        }

        // ---- O += P V (3-pass split) with ldmatrix V fragments ----
#pragma unroll
        for (int js = 0; js < 4; js++) {
#pragma unroll
            for (int ntp = 0; ntp < 4; ntp++) {
                uint32_t off = (ntp * 16 + l15) * 144 + js * 32 + lhi;
                uint32_t vhp[4], vlp[4];
                ldsm4(vhp, stg + ATV_OFF + off);
                ldsm4(vlp, stg + ATVL_OFF + off);
#pragma unroll
                for (int sub = 0; sub < 2; sub++) {
                    int nt = ntp * 2 + sub;
                    uint32_t vh2[2] = { vhp[sub], vhp[2 + sub] };
                    uint32_t vl2[2] = { vlp[sub], vlp[2 + sub] };
                    mma16816(O[nt], pha[js], vh2);
                    mma16816(O[nt], pha[js], vl2);
                    mma16816(O[nt], pla[js], vh2);
                }
            }
        }
        __syncthreads();
    }

    l0 += __shfl_xor_sync(0xFFFFFFFFu, l0, 1);
    l0 += __shfl_xor_sync(0xFFFFFFFFu, l0, 2);
    l1 += __shfl_xor_sync(0xFFFFFFFFu, l1, 1);
    l1 += __shfl_xor_sync(0xFFFFFFFFu, l1, 2);

    float inv0 = spikes[b * Tn + r0g] / l0;
    float inv1 = spikes[b * Tn + r1g] / l1;

#pragma unroll
    for (int nt = 0; nt < 8; nt++) {
        int col = h * 64 + nt * 8 + 2 * (lane & 3);
        float2 o0 = make_float2(O[nt][0] * inv0, O[nt][1] * inv0);
        float2 o1 = make_float2(O[nt][2] * inv1, O[nt][3] * inv1);
        *(float2*)&y[((size_t)(b * Tn + r0g)) * Cn + col] = o0;
        *(float2*)&y[((size_t)(b * Tn + r1g)) * Cn + col] = o1;
    }
}

// ---------------- launcher ----------------
extern "C" void kernel_launch(void* const* d_in, const int* in_sizes, int n_in,
                              void* d_out, int out_size) {
    const float* x    = (const float*)d_in[0];
    const float* Wqkv = (const float*)d_in[1];
    const float* bqkv = (const float*)d_in[2];
    const float* Wout = (const float*)d_in[3];
    const float* bout = (const float*)d_in[4];
    const float* wsur = (const float*)d_in[5];
    const float* bsur = (const float*)d_in[6];
    const float* thr  = (const float*)d_in[7];
    float* out = (float*)d_out;

    float *qkv, *spk, *y;
    __nv_bfloat16 *xh, *xl, *yh, *yl, *wqh, *wql, *woh, *wol;
    __nv_bfloat16 *qth, *qtl, *kth, *ktl, *vth, *vtl;
    cudaGetSymbolAddress((void**)&qkv, g_qkv);
    cudaGetSymbolAddress((void**)&spk, g_spk);
    cudaGetSymbolAddress((void**)&y, g_y);
    cudaGetSymbolAddress((void**)&xh, g_xh);
    cudaGetSymbolAddress((void**)&xl, g_xl);
    cudaGetSymbolAddress((void**)&yh, g_yh);
    cudaGetSymbolAddress((void**)&yl, g_yl);
    cudaGetSymbolAddress((void**)&wqh, g_wqh);
    cudaGetSymbolAddress((void**)&wql, g_wql);
    cudaGetSymbolAddress((void**)&woh, g_woh);
    cudaGetSymbolAddress((void**)&wol, g_wol);
    cudaGetSymbolAddress((void**)&qth, g_qth);
    cudaGetSymbolAddress((void**)&qtl, g_qtl);
    cudaGetSymbolAddress((void**)&kth, g_kth);
    cudaGetSymbolAddress((void**)&ktl, g_ktl);
    cudaGetSymbolAddress((void**)&vth, g_vth);
    cudaGetSymbolAddress((void**)&vtl, g_vtl);

    cudaFuncSetAttribute(mma_gemm_kernel, cudaFuncAttributeMaxDynamicSharedMemorySize, GEMM_SMEM);
    cudaFuncSetAttribute(attn_mma_kernel, cudaFuncAttributeMaxDynamicSharedMemorySize, ATTN_SMEM);

    // 1. spikes
    spike_kernel<<<MR, 256>>>(x, wsur, bsur, thr, spk);
    // 2. split-bf16 conversions
    conv_rows_kernel<<<(MR * Cn) / 256, 256>>>(x, xh, xl);
    convT_kernel<<<dim3(3 * Cn / 32, Cn / 32), dim3(32, 8)>>>(Wqkv, wqh, wql, Cn, 3 * Cn);
    // 3. qkv = x @ W_qkv + b
    mma_gemm_kernel<<<dim3(3 * Cn / 128, MR / 128), 256, GEMM_SMEM>>>(
        xh, xl, wqh, wql, bqkv, qkv, 3 * Cn, Cn);
    // 4. hyperbolic transform -> split-bf16 q,k,v^T
    transform_kernel<<<dim3(MR / 32, Hn), 256>>>(qkv, qth, qtl, kth, ktl, vth, vtl);
    // 5. flash attention (tensor cores)
    attn_mma_kernel<<<512, 256, ATTN_SMEM>>>(qth, qtl, kth, ktl, vth, vtl, spk, y);
    // 6. out projection
    conv_rows_kernel<<<(MR * Cn) / 256, 256>>>(y, yh, yl);
    convT_kernel<<<dim3(Cn / 32, Cn / 32), dim3(32, 8)>>>(Wout, woh, wol, Cn, Cn);
    mma_gemm_kernel<<<dim3(Cn / 128, MR / 128), 256, GEMM_SMEM>>>(
        yh, yl, woh, wol, bout, out, Cn, Cn);
}